// round 2
// baseline (speedup 1.0000x reference)
#include <cuda_runtime.h>
#include <cstdint>

#define D_MODEL 2048
#define NHEADS  16
#define HD      128
#define BATCH   2
#define TQ      1024
#define XLLEN   1024
#define KVLEN   2048            // XL + T
#define MROWS   (BATCH * TQ)    // 2048

// ---------------- scratch (device globals: no runtime allocation) ----------------
__device__ float g_qkv[(size_t)MROWS * 3 * D_MODEL];          // 50 MB
__device__ float g_q  [(size_t)BATCH * NHEADS * TQ * HD];     // 16 MB
__device__ float g_kf [(size_t)BATCH * NHEADS * KVLEN * HD];  // 32 MB
__device__ float g_vf [(size_t)BATCH * NHEADS * KVLEN * HD];  // 32 MB
__device__ float g_y  [(size_t)MROWS * D_MODEL];              // 16 MB

// =====================================================================
// NT SGEMM: C[M,N] = A[M,K] * B[N,K]^T, all row-major, fp32.
// 128x128 tile, BK=16, 256 threads, 8x8 per thread (4+4 split blocking),
// double-buffered shared memory, one __syncthreads per K-step.
// Requires M%128==0, N%128==0, K%16==0.
// =====================================================================
__global__ __launch_bounds__(256) void sgemm_nt(
    const float* __restrict__ A, const float* __restrict__ B,
    float* __restrict__ C, int M, int N, int K)
{
    __shared__ float Ast[2][16][132];   // [k][m], padded
    __shared__ float Bst[2][16][132];   // [k][n], padded

    const int tid = threadIdx.x;
    const int mb = blockIdx.y * 128;
    const int nb = blockIdx.x * 128;
    const int lr = tid >> 2;            // 0..63
    const int lc = (tid & 3) << 2;      // 0,4,8,12
    const int tx = tid & 15, ty = tid >> 4;

    const float* Ap = A + (size_t)(mb + lr) * K + lc;
    const float* Bp = B + (size_t)(nb + lr) * K + lc;
    const size_t rstep = (size_t)64 * K;

    float4 a0 = *(const float4*)(Ap);
    float4 a1 = *(const float4*)(Ap + rstep);
    float4 b0 = *(const float4*)(Bp);
    float4 b1 = *(const float4*)(Bp + rstep);
#pragma unroll
    for (int u = 0; u < 4; u++) {
        Ast[0][lc + u][lr]      = ((const float*)&a0)[u];
        Ast[0][lc + u][lr + 64] = ((const float*)&a1)[u];
        Bst[0][lc + u][lr]      = ((const float*)&b0)[u];
        Bst[0][lc + u][lr + 64] = ((const float*)&b1)[u];
    }
    __syncthreads();

    float acc[8][8];
#pragma unroll
    for (int i = 0; i < 8; i++)
#pragma unroll
        for (int j = 0; j < 8; j++) acc[i][j] = 0.f;

    const int nk = K >> 4;
    int cur = 0;
    for (int kt = 0; kt < nk; kt++) {
        if (kt + 1 < nk) {
            const float* Ap2 = Ap + (size_t)(kt + 1) * 16;
            const float* Bp2 = Bp + (size_t)(kt + 1) * 16;
            a0 = *(const float4*)(Ap2);
            a1 = *(const float4*)(Ap2 + rstep);
            b0 = *(const float4*)(Bp2);
            b1 = *(const float4*)(Bp2 + rstep);
        }
#pragma unroll
        for (int k = 0; k < 16; k++) {
            float4 ra0 = *(const float4*)&Ast[cur][k][ty * 4];
            float4 ra1 = *(const float4*)&Ast[cur][k][64 + ty * 4];
            float4 rb0 = *(const float4*)&Bst[cur][k][tx * 4];
            float4 rb1 = *(const float4*)&Bst[cur][k][64 + tx * 4];
            float ar[8] = {ra0.x, ra0.y, ra0.z, ra0.w, ra1.x, ra1.y, ra1.z, ra1.w};
            float br[8] = {rb0.x, rb0.y, rb0.z, rb0.w, rb1.x, rb1.y, rb1.z, rb1.w};
#pragma unroll
            for (int i = 0; i < 8; i++)
#pragma unroll
                for (int j = 0; j < 8; j++)
                    acc[i][j] = fmaf(ar[i], br[j], acc[i][j]);
        }
        if (kt + 1 < nk) {
            const int nxt = cur ^ 1;
#pragma unroll
            for (int u = 0; u < 4; u++) {
                Ast[nxt][lc + u][lr]      = ((const float*)&a0)[u];
                Ast[nxt][lc + u][lr + 64] = ((const float*)&a1)[u];
                Bst[nxt][lc + u][lr]      = ((const float*)&b0)[u];
                Bst[nxt][lc + u][lr + 64] = ((const float*)&b1)[u];
            }
        }
        __syncthreads();
        cur ^= 1;
    }

#pragma unroll
    for (int rg = 0; rg < 2; rg++)
#pragma unroll
        for (int i = 0; i < 4; i++) {
            size_t row = (size_t)(mb + rg * 64 + ty * 4 + i);
            float* Cp = C + row * N + nb;
            int ai = rg * 4 + i;
            float4 c0 = make_float4(acc[ai][0], acc[ai][1], acc[ai][2], acc[ai][3]);
            float4 c1 = make_float4(acc[ai][4], acc[ai][5], acc[ai][6], acc[ai][7]);
            *(float4*)(Cp + tx * 4)      = c0;
            *(float4*)(Cp + 64 + tx * 4) = c1;
        }
}

// =====================================================================
// XL prep: k_full[:, :XL] = reshape(k_xl + pos_emb), v_full[:, :XL] = v_xl
// one thread per element of (B, XL, D_MODEL)
// =====================================================================
__global__ void xl_prep(const float* __restrict__ kxl, const float* __restrict__ vxl,
                        const float* __restrict__ pos)
{
    int idx = blockIdx.x * blockDim.x + threadIdx.x;   // 4,194,304 exact
    int c = idx & 2047;
    int t = (idx >> 11) & 1023;
    int b = idx >> 21;
    int h = c >> 7, d = c & 127;
    size_t dst = ((size_t)((b * NHEADS + h) * KVLEN + t)) * HD + d;
    g_kf[dst] = kxl[idx] + pos[t * 2048 + c];
    g_vf[dst] = vxl[idx];
}

// =====================================================================
// RoPE + split qkv -> q (bh-major), k -> k_full[XL:], v -> v_full[XL:]
// one thread per (b, t, h, dpair); interleaved-pair RoPE.
// =====================================================================
__global__ void rope_split(const float* __restrict__ cosb, const float* __restrict__ sinb)
{
    int idx = blockIdx.x * blockDim.x + threadIdx.x;   // 2,097,152 exact
    int dp = idx & 63;
    int h  = (idx >> 6) & 15;
    int t  = (idx >> 10) & 1023;
    int b  = idx >> 20;
    int m  = b * TQ + t;

    const float* base = g_qkv + (size_t)m * (3 * D_MODEL) + h * HD + 2 * dp;
    float c = cosb[t * 64 + dp];
    float s = sinb[t * 64 + dp];
    float2 qv = *(const float2*)(base);
    float2 kv = *(const float2*)(base + D_MODEL);
    float2 vv = *(const float2*)(base + 2 * D_MODEL);
    float2 qo = make_float2(qv.x * c - qv.y * s, qv.x * s + qv.y * c);
    float2 ko = make_float2(kv.x * c - kv.y * s, kv.x * s + kv.y * c);

    size_t bh = (size_t)(b * NHEADS + h);
    *(float2*)&g_q [(bh * TQ + t) * HD + 2 * dp]           = qo;
    *(float2*)&g_kf[(bh * KVLEN + XLLEN + t) * HD + 2 * dp] = ko;
    *(float2*)&g_vf[(bh * KVLEN + XLLEN + t) * HD + 2 * dp] = vv;
}

// =====================================================================
// Flash attention fp32: BQ=64, BK=64, D=128, 256 threads.
// Q,K stored transposed [128][68] in smem for conflict-free float4 LDS.
// P tile aliases the K tile. Online softmax stats via smem rows.
// grid = (T/64, B*H)
// =====================================================================
#define ATTN_SMEM_FLOATS (8704 + 8704 + 8192 + 1088 + 256)
#define ATTN_SMEM_BYTES  (ATTN_SMEM_FLOATS * 4)

__global__ __launch_bounds__(256, 2) void attn_kernel(const int* __restrict__ flag)
{
    extern __shared__ float smf[];
    float* Qst  = smf;                 // [128][68]  (k-major, transposed)
    float* Kst  = smf + 8704;          // [128][68]
    float* Vs   = smf + 2 * 8704;      // [64][128]
    float* red  = Vs + 8192;           // [64][17]
    float* mrow = red + 1088;          // [64]
    float* lrow = mrow + 64;           // [64]
    float* nmrw = lrow + 64;           // [64]
    float* arow = nmrw + 64;           // [64]
    float* Ps   = Kst;                 // alias: [64][65] fits in 8704

    const int tid = threadIdx.x;
    const int tx = tid & 15, ty = tid >> 4;
    const int qt = blockIdx.x;
    const int bh = blockIdx.y;
    const int b = bh >> 4, h = bh & 15;
    const int qbase = qt * 64;
    const float* Qb = g_q  + (size_t)bh * (TQ * HD);
    const float* Kb = g_kf + (size_t)bh * (KVLEN * HD);
    const float* Vb = g_vf + (size_t)bh * (KVLEN * HD);
    const int causal = *flag;

    if (tid < 64) { mrow[tid] = -1e30f; lrow[tid] = 0.f; }

    // load Q tile transposed
    for (int e = tid * 4; e < 64 * 128; e += 1024) {
        int r = e >> 7, kk = e & 127;
        float4 v = *(const float4*)&Qb[(size_t)(qbase + r) * HD + kk];
        Qst[(kk + 0) * 68 + r] = v.x;
        Qst[(kk + 1) * 68 + r] = v.y;
        Qst[(kk + 2) * 68 + r] = v.z;
        Qst[(kk + 3) * 68 + r] = v.w;
    }
    __syncthreads();

    float o[4][8];
#pragma unroll
    for (int i = 0; i < 4; i++)
#pragma unroll
        for (int u = 0; u < 8; u++) o[i][u] = 0.f;

    const int r0 = ty * 4, c0 = tx * 4;
    const float scale = 0.08838834764831845f;   // 1/sqrt(128)

    int ntile = causal ? (qt + 17) : 32;
    if (ntile > 32) ntile = 32;

    for (int kt = 0; kt < ntile; kt++) {
        const int kbase = kt * 64;
        // load K tile transposed + V tile straight
        for (int e = tid * 4; e < 64 * 128; e += 1024) {
            int r = e >> 7, kk = e & 127;
            float4 kv = *(const float4*)&Kb[(size_t)(kbase + r) * HD + kk];
            Kst[(kk + 0) * 68 + r] = kv.x;
            Kst[(kk + 1) * 68 + r] = kv.y;
            Kst[(kk + 2) * 68 + r] = kv.z;
            Kst[(kk + 3) * 68 + r] = kv.w;
            *(float4*)&Vs[r * 128 + kk] = *(const float4*)&Vb[(size_t)(kbase + r) * HD + kk];
        }
        __syncthreads();                                   // sync1

        // S = Q @ K^T  (4x4 per thread)
        float s[4][4];
#pragma unroll
        for (int i = 0; i < 4; i++)
#pragma unroll
            for (int j = 0; j < 4; j++) s[i][j] = 0.f;
#pragma unroll 8
        for (int kk = 0; kk < 128; kk++) {
            float4 a  = *(const float4*)&Qst[kk * 68 + r0];
            float4 bb = *(const float4*)&Kst[kk * 68 + c0];
            float av[4] = {a.x, a.y, a.z, a.w};
            float bv[4] = {bb.x, bb.y, bb.z, bb.w};
#pragma unroll
            for (int i = 0; i < 4; i++)
#pragma unroll
                for (int j = 0; j < 4; j++)
                    s[i][j] = fmaf(av[i], bv[j], s[i][j]);
        }

        // scale + mask + local row max
#pragma unroll
        for (int i = 0; i < 4; i++) {
            float lm = -1e30f;
#pragma unroll
            for (int j = 0; j < 4; j++) {
                float v = s[i][j] * scale;
                if (causal && (kbase + c0 + j) > (qbase + r0 + i + (KVLEN - TQ))) v = -1e30f;
                s[i][j] = v;
                lm = fmaxf(lm, v);
            }
            red[(r0 + i) * 17 + tx] = lm;
        }
        __syncthreads();                                   // sync2

        if (tid < 64) {
            float t = red[tid * 17];
#pragma unroll
            for (int u = 1; u < 16; u++) t = fmaxf(t, red[tid * 17 + u]);
            float mo = mrow[tid];
            float nm = fmaxf(mo, t);
            mrow[tid] = nm;
            nmrw[tid] = nm;
            arow[tid] = __expf(mo - nm);
        }
        __syncthreads();                                   // sync3

        // P = exp(S - m), rescale O, stage P and row-sum partials
        float ls[4];
#pragma unroll
        for (int i = 0; i < 4; i++) {
            float nm = nmrw[r0 + i];
            float al = arow[r0 + i];
            ls[i] = 0.f;
#pragma unroll
            for (int j = 0; j < 4; j++) {
                float p = __expf(s[i][j] - nm);
                s[i][j] = p;
                ls[i] += p;
            }
#pragma unroll
            for (int u = 0; u < 8; u++) o[i][u] *= al;
        }
#pragma unroll
        for (int i = 0; i < 4; i++) {
            red[(r0 + i) * 17 + tx] = ls[i];
#pragma unroll
            for (int j = 0; j < 4; j++) Ps[(r0 + i) * 65 + c0 + j] = s[i][j];
        }
        __syncthreads();                                   // sync4

        if (tid < 64) {
            float t = 0.f;
#pragma unroll
            for (int u = 0; u < 16; u++) t += red[tid * 17 + u];
            lrow[tid] = lrow[tid] * arow[tid] + t;
        }

        // O += P @ V
#pragma unroll 4
        for (int j = 0; j < 64; j++) {
            float4 v0 = *(const float4*)&Vs[j * 128 + c0];
            float4 v1 = *(const float4*)&Vs[j * 128 + 64 + c0];
#pragma unroll
            for (int i = 0; i < 4; i++) {
                float p = Ps[(r0 + i) * 65 + j];
                o[i][0] = fmaf(p, v0.x, o[i][0]);
                o[i][1] = fmaf(p, v0.y, o[i][1]);
                o[i][2] = fmaf(p, v0.z, o[i][2]);
                o[i][3] = fmaf(p, v0.w, o[i][3]);
                o[i][4] = fmaf(p, v1.x, o[i][4]);
                o[i][5] = fmaf(p, v1.y, o[i][5]);
                o[i][6] = fmaf(p, v1.z, o[i][6]);
                o[i][7] = fmaf(p, v1.w, o[i][7]);
            }
        }
        __syncthreads();                                   // sync5
    }

    // epilogue: O / l -> y in (b, t, h*128+d) layout (feeds proj GEMM directly)
    float* Yb = g_y + ((size_t)(b * TQ + qbase)) * D_MODEL + h * HD;
#pragma unroll
    for (int i = 0; i < 4; i++) {
        float inv = 1.0f / lrow[r0 + i];
        float4 w0 = make_float4(o[i][0] * inv, o[i][1] * inv, o[i][2] * inv, o[i][3] * inv);
        float4 w1 = make_float4(o[i][4] * inv, o[i][5] * inv, o[i][6] * inv, o[i][7] * inv);
        *(float4*)&Yb[(size_t)(r0 + i) * D_MODEL + c0]      = w0;
        *(float4*)&Yb[(size_t)(r0 + i) * D_MODEL + 64 + c0] = w1;
    }
}

// =====================================================================
// launch
// =====================================================================
extern "C" void kernel_launch(void* const* d_in, const int* in_sizes, int n_in,
                              void* d_out, int out_size)
{
    const float* x     = (const float*)d_in[0];
    const float* cosb  = (const float*)d_in[1];
    const float* sinb  = (const float*)d_in[2];
    const float* kxl   = (const float*)d_in[3];
    const float* vxl   = (const float*)d_in[4];
    const float* pos   = (const float*)d_in[5];
    const float* wqkv  = (const float*)d_in[6];
    const float* wproj = (const float*)d_in[7];
    const int*   flag  = (const int*)d_in[8];
    float*       out   = (float*)d_out;

    float *qkv, *y;
    cudaGetSymbolAddress((void**)&qkv, g_qkv);
    cudaGetSymbolAddress((void**)&y,   g_y);

    cudaFuncSetAttribute(attn_kernel, cudaFuncAttributeMaxDynamicSharedMemorySize,
                         ATTN_SMEM_BYTES);

    // 1) qkv = x @ w_qkv^T : (2048 x 6144 x 2048)
    sgemm_nt<<<dim3(3 * D_MODEL / 128, MROWS / 128), 256>>>(
        x, wqkv, qkv, MROWS, 3 * D_MODEL, D_MODEL);

    // 2) XL prep: k_full[:XL] = k_xl + pos_emb, v_full[:XL] = v_xl
    xl_prep<<<(BATCH * XLLEN * D_MODEL) / 256, 256>>>(kxl, vxl, pos);

    // 3) RoPE + scatter q/k/v
    rope_split<<<(BATCH * TQ * NHEADS * 64) / 256, 256>>>(cosb, sinb);

    // 4) flash attention -> g_y (already in (b,t,c) layout)
    attn_kernel<<<dim3(TQ / 64, BATCH * NHEADS), 256, ATTN_SMEM_BYTES>>>(flag);

    // 5) out = y @ w_proj^T : (2048 x 2048 x 2048)
    sgemm_nt<<<dim3(D_MODEL / 128, MROWS / 128), 256>>>(
        y, wproj, out, MROWS, D_MODEL, D_MODEL);
}

// round 4
// speedup vs baseline: 2.1893x; 2.1893x over previous
#include <cuda_runtime.h>
#include <cuda_bf16.h>
#include <cstdint>

#define D_MODEL 2048
#define NHEADS  16
#define HD      128
#define BATCH   2
#define TQ      1024
#define XLLEN   1024
#define KVLEN   2048
#define MROWS   (BATCH * TQ)    // 2048

// ---------------- scratch (device globals) ----------------
__device__ float g_qkv[(size_t)MROWS * 3 * D_MODEL];
__device__ float g_y  [(size_t)MROWS * D_MODEL];
__device__ __nv_bfloat16 g_qh[(size_t)BATCH * NHEADS * TQ * HD];
__device__ __nv_bfloat16 g_ql[(size_t)BATCH * NHEADS * TQ * HD];
__device__ __nv_bfloat16 g_kh[(size_t)BATCH * NHEADS * KVLEN * HD];
__device__ __nv_bfloat16 g_kl[(size_t)BATCH * NHEADS * KVLEN * HD];
__device__ __nv_bfloat16 g_vh[(size_t)BATCH * NHEADS * KVLEN * HD];
__device__ __nv_bfloat16 g_vl[(size_t)BATCH * NHEADS * KVLEN * HD];
__device__ __nv_bfloat16 g_ah[(size_t)MROWS * D_MODEL];
__device__ __nv_bfloat16 g_al[(size_t)MROWS * D_MODEL];
__device__ __nv_bfloat16 g_bh[(size_t)3 * D_MODEL * D_MODEL];
__device__ __nv_bfloat16 g_bl[(size_t)3 * D_MODEL * D_MODEL];

// ======================= PTX helpers (baseline sm_80+ ISA) =======================
__device__ __forceinline__ uint32_t smem_u32(const void* p) {
    uint32_t a;
    asm("{ .reg .u64 t; cvta.to.shared.u64 t, %1; cvt.u32.u64 %0, t; }" : "=r"(a) : "l"(p));
    return a;
}
__device__ __forceinline__ void ldm4(uint32_t* r, uint32_t a) {
    asm volatile("ldmatrix.sync.aligned.m8n8.x4.shared.b16 {%0,%1,%2,%3}, [%4];"
                 : "=r"(r[0]), "=r"(r[1]), "=r"(r[2]), "=r"(r[3]) : "r"(a));
}
__device__ __forceinline__ void ldm4t(uint32_t* r, uint32_t a) {
    asm volatile("ldmatrix.sync.aligned.m8n8.x4.trans.shared.b16 {%0,%1,%2,%3}, [%4];"
                 : "=r"(r[0]), "=r"(r[1]), "=r"(r[2]), "=r"(r[3]) : "r"(a));
}
__device__ __forceinline__ void mma16816(float* d, const uint32_t* a, uint32_t b0, uint32_t b1) {
    asm volatile("mma.sync.aligned.m16n8k16.row.col.f32.bf16.bf16.f32 "
                 "{%0,%1,%2,%3}, {%4,%5,%6,%7}, {%8,%9}, {%0,%1,%2,%3};"
                 : "+f"(d[0]), "+f"(d[1]), "+f"(d[2]), "+f"(d[3])
                 : "r"(a[0]), "r"(a[1]), "r"(a[2]), "r"(a[3]), "r"(b0), "r"(b1));
}
__device__ __forceinline__ void cpa16(uint32_t dst, const void* src) {
    asm volatile("cp.async.cg.shared.global [%0], [%1], 16;" :: "r"(dst), "l"(src));
}
__device__ __forceinline__ void cpa_commit() { asm volatile("cp.async.commit_group;" ::: "memory"); }
__device__ __forceinline__ void cpa_wait1()  { asm volatile("cp.async.wait_group 1;" ::: "memory"); }
__device__ __forceinline__ void cpa_wait0()  { asm volatile("cp.async.wait_group 0;" ::: "memory"); }

__device__ __forceinline__ void split2(float x, __nv_bfloat16& h, __nv_bfloat16& l) {
    h = __float2bfloat16(x);
    l = __float2bfloat16(x - __bfloat162float(h));
}

// =====================================================================
// split fp32 -> bf16 hi/lo (for GEMM operands)
// =====================================================================
__global__ void split_bf16_kernel(const float* __restrict__ src,
                                  __nv_bfloat16* __restrict__ hi,
                                  __nv_bfloat16* __restrict__ lo, int n4)
{
    int i = blockIdx.x * blockDim.x + threadIdx.x;
    if (i >= n4) return;
    float4 v = ((const float4*)src)[i];
    float vv[4] = {v.x, v.y, v.z, v.w};
    __nv_bfloat16 h[4], l[4];
#pragma unroll
    for (int u = 0; u < 4; u++) split2(vv[u], h[u], l[u]);
    *(uint2*)(hi + (size_t)i * 4) = *(uint2*)h;
    *(uint2*)(lo + (size_t)i * 4) = *(uint2*)l;
}

// =====================================================================
// mma.sync split-bf16 NT GEMM: C[M,N] = A[M,K]*B[N,K]^T, fp32 out.
// 128x128 tile, BK=32, 8 warps (warp tile 64x32), cp.async 2-stage.
// smem tile row stride = 40 elems (80B): conflict-free for ldmatrix.
// =====================================================================
#define GTILE_B  10240            // 128 rows x 80B
#define GSTAGE_B (4 * GTILE_B)    // Ah, Al, Bh, Bl
#define GEMM_SMEM (2 * GSTAGE_B)  // 81920

__global__ __launch_bounds__(256) void gemm_mma(
    const __nv_bfloat16* __restrict__ Ah, const __nv_bfloat16* __restrict__ Al,
    const __nv_bfloat16* __restrict__ Bh, const __nv_bfloat16* __restrict__ Bl,
    float* __restrict__ C, int M, int N, int K)
{
    extern __shared__ __align__(16) char smraw[];
    const uint32_t sb = smem_u32(smraw);
    const int tid = threadIdx.x, wid = tid >> 5, lane = tid & 31;
    const int wm = wid & 1, wn = wid >> 1;
    const int mb = blockIdx.y * 128, nb = blockIdx.x * 128;

    const __nv_bfloat16* srcs[4] = {
        Ah + (size_t)mb * K, Al + (size_t)mb * K,
        Bh + (size_t)nb * K, Bl + (size_t)nb * K };

    const int NKB = K >> 5;
    const int lrow = tid >> 2, lkc = tid & 3;   // load mapping helpers

    // prologue: issue stage 0
    {
        const uint32_t st = sb;
#pragma unroll
        for (int t = 0; t < 4; t++) {
            const __nv_bfloat16* g = srcs[t];
#pragma unroll
            for (int i = 0; i < 2; i++) {
                int c = tid + i * 256;          // 0..511
                int row = c >> 2, kc = c & 3;
                cpa16(st + t * GTILE_B + row * 80 + kc * 16,
                      g + (size_t)row * K + kc * 8);
            }
        }
        cpa_commit();
    }

    float acc[4][4][4];
#pragma unroll
    for (int a = 0; a < 4; a++)
#pragma unroll
        for (int b = 0; b < 4; b++)
#pragma unroll
            for (int e = 0; e < 4; e++) acc[a][b][e] = 0.f;

    for (int kb = 0; kb < NKB; kb++) {
        if (kb + 1 < NKB) {
            const uint32_t st = sb + ((kb + 1) & 1) * GSTAGE_B;
            const int ko = (kb + 1) * 32;
#pragma unroll
            for (int t = 0; t < 4; t++) {
                const __nv_bfloat16* g = srcs[t];
#pragma unroll
                for (int i = 0; i < 2; i++) {
                    int c = tid + i * 256;
                    int row = c >> 2, kc = c & 3;
                    cpa16(st + t * GTILE_B + row * 80 + kc * 16,
                          g + (size_t)row * K + ko + kc * 8);
                }
            }
            cpa_commit();
            cpa_wait1();
        } else {
            cpa_wait0();
        }
        __syncthreads();

        const uint32_t st = sb + (kb & 1) * GSTAGE_B;
        const uint32_t arow = (uint32_t)(wm * 64 + (lane & 15)) * 80;
        const uint32_t brow = (uint32_t)(wn * 32 + (lane & 15)) * 80;
#pragma unroll
        for (int ks = 0; ks < 2; ks++) {
            const uint32_t koff = ks * 32 + (lane >> 4) * 16;
            uint32_t Af[4][4], Bh2[2][4], Bl2[2][4];
#pragma unroll
            for (int mt = 0; mt < 4; mt++)
                ldm4(Af[mt], st + arow + mt * 16 * 80 + koff);
#pragma unroll
            for (int np = 0; np < 2; np++)
                ldm4(Bh2[np], st + 2 * GTILE_B + brow + np * 16 * 80 + koff);
#pragma unroll
            for (int np = 0; np < 2; np++)
                ldm4(Bl2[np], st + 3 * GTILE_B + brow + np * 16 * 80 + koff);
#pragma unroll
            for (int mt = 0; mt < 4; mt++)
#pragma unroll
                for (int nt = 0; nt < 4; nt++)
                    mma16816(acc[mt][nt], Af[mt], Bh2[nt >> 1][nt & 1], Bh2[nt >> 1][(nt & 1) + 2]);
#pragma unroll
            for (int mt = 0; mt < 4; mt++)
#pragma unroll
                for (int nt = 0; nt < 4; nt++)
                    mma16816(acc[mt][nt], Af[mt], Bl2[nt >> 1][nt & 1], Bl2[nt >> 1][(nt & 1) + 2]);
#pragma unroll
            for (int mt = 0; mt < 4; mt++)
                ldm4(Af[mt], st + GTILE_B + arow + mt * 16 * 80 + koff);
#pragma unroll
            for (int mt = 0; mt < 4; mt++)
#pragma unroll
                for (int nt = 0; nt < 4; nt++)
                    mma16816(acc[mt][nt], Af[mt], Bh2[nt >> 1][nt & 1], Bh2[nt >> 1][(nt & 1) + 2]);
        }
        __syncthreads();
    }

    // epilogue
#pragma unroll
    for (int mt = 0; mt < 4; mt++) {
        int row0 = mb + wm * 64 + mt * 16 + (lane >> 2);
#pragma unroll
        for (int nt = 0; nt < 4; nt++) {
            int col = nb + wn * 32 + nt * 8 + (lane & 3) * 2;
            *(float2*)&C[(size_t)row0 * N + col]       = make_float2(acc[mt][nt][0], acc[mt][nt][1]);
            *(float2*)&C[(size_t)(row0 + 8) * N + col] = make_float2(acc[mt][nt][2], acc[mt][nt][3]);
        }
    }
    (void)lrow; (void)lkc;
}

// =====================================================================
// XL prep: kh/kl/vh/vl[:, :XL] from (k_xl + pos_emb), v_xl  (bf16 hi/lo)
// 2 channel-elems per thread
// =====================================================================
__global__ void xl_prep(const float* __restrict__ kxl, const float* __restrict__ vxl,
                        const float* __restrict__ pos)
{
    int idx = blockIdx.x * blockDim.x + threadIdx.x;   // B*XL*D/2 = 2,097,152
    int c2 = idx & 1023;
    int t  = (idx >> 10) & 1023;
    int b  = idx >> 20;
    int c = c2 * 2;
    int h = c >> 7, d = c & 127;
    size_t src = ((size_t)(b * XLLEN + t)) * D_MODEL + c;
    float2 kv = *(const float2*)(kxl + src);
    float2 pv = *(const float2*)(pos + (size_t)t * D_MODEL + c);
    float2 vv = *(const float2*)(vxl + src);
    float k0 = kv.x + pv.x, k1 = kv.y + pv.y;
    __nv_bfloat16 h0, l0, h1, l1, vh0, vl0, vh1, vl1;
    split2(k0, h0, l0); split2(k1, h1, l1);
    split2(vv.x, vh0, vl0); split2(vv.y, vh1, vl1);
    size_t dst = ((size_t)((b * NHEADS + h) * KVLEN + t)) * HD + d;
    *(__nv_bfloat162*)&g_kh[dst] = __nv_bfloat162{h0, h1};
    *(__nv_bfloat162*)&g_kl[dst] = __nv_bfloat162{l0, l1};
    *(__nv_bfloat162*)&g_vh[dst] = __nv_bfloat162{vh0, vh1};
    *(__nv_bfloat162*)&g_vl[dst] = __nv_bfloat162{vl0, vl1};
}

// =====================================================================
// RoPE + split qkv -> bf16 hi/lo q, k_full[XL:], v_full[XL:]
// =====================================================================
__global__ void rope_split(const float* __restrict__ cosb, const float* __restrict__ sinb)
{
    int idx = blockIdx.x * blockDim.x + threadIdx.x;   // 2,097,152
    int dp = idx & 63;
    int h  = (idx >> 6) & 15;
    int t  = (idx >> 10) & 1023;
    int b  = idx >> 20;
    int m  = b * TQ + t;

    const float* base = g_qkv + (size_t)m * (3 * D_MODEL) + h * HD + 2 * dp;
    float c = cosb[t * 64 + dp];
    float s = sinb[t * 64 + dp];
    float2 qv = *(const float2*)(base);
    float2 kv = *(const float2*)(base + D_MODEL);
    float2 vv = *(const float2*)(base + 2 * D_MODEL);
    float q0 = qv.x * c - qv.y * s, q1 = qv.x * s + qv.y * c;
    float k0 = kv.x * c - kv.y * s, k1 = kv.x * s + kv.y * c;

    __nv_bfloat16 a0, a1, a2, a3;
    size_t bh = (size_t)(b * NHEADS + h);
    size_t qd = (bh * TQ + t) * HD + 2 * dp;
    size_t kd = (bh * KVLEN + XLLEN + t) * HD + 2 * dp;
    split2(q0, a0, a1); split2(q1, a2, a3);
    *(__nv_bfloat162*)&g_qh[qd] = __nv_bfloat162{a0, a2};
    *(__nv_bfloat162*)&g_ql[qd] = __nv_bfloat162{a1, a3};
    split2(k0, a0, a1); split2(k1, a2, a3);
    *(__nv_bfloat162*)&g_kh[kd] = __nv_bfloat162{a0, a2};
    *(__nv_bfloat162*)&g_kl[kd] = __nv_bfloat162{a1, a3};
    split2(vv.x, a0, a1); split2(vv.y, a2, a3);
    *(__nv_bfloat162*)&g_vh[kd] = __nv_bfloat162{a0, a2};
    *(__nv_bfloat162*)&g_vl[kd] = __nv_bfloat162{a1, a3};
}

// =====================================================================
// Flash attention, split-bf16 mma.sync: BQ=64, BK=64, D=128, 8 warps.
// Q/K/V tiles: [64][136] bf16 (272B rows); P: [64][72] (144B rows).
// K/V double-buffered via cp.async.
// =====================================================================
#define AQH 0
#define AQL 17408
#define AKV 34816
#define AKVSTR 69632
#define AKHOF 0
#define AKLOF 17408
#define AVHOF 34816
#define AVLOF 52224
#define APH 174080
#define APL 183296
#define ARM 192512
#define ARS 193536
#define AMR 194560
#define ALR 194816
#define ANM 195072
#define AAR 195328
#define ATTN_SMEM 195584

__global__ __launch_bounds__(256) void attn_kernel(const int* __restrict__ flag)
{
    extern __shared__ __align__(16) char smraw[];
    const uint32_t sb = smem_u32(smraw);
    float* RM = (float*)(smraw + ARM);
    float* RS = (float*)(smraw + ARS);
    float* MR = (float*)(smraw + AMR);
    float* LR = (float*)(smraw + ALR);
    float* NM = (float*)(smraw + ANM);
    float* AR = (float*)(smraw + AAR);

    const int tid = threadIdx.x, wid = tid >> 5, lane = tid & 31;
    const int wm = wid & 1, wn = wid >> 1;
    const int qt = blockIdx.x, bh = blockIdx.y;
    const int b = bh >> 4, h = bh & 15;
    const int qbase = qt * 64;
    const int causal = *flag;

    const __nv_bfloat16* Qh = g_qh + (size_t)bh * (TQ * HD);
    const __nv_bfloat16* Ql = g_ql + (size_t)bh * (TQ * HD);
    const __nv_bfloat16* Kh = g_kh + (size_t)bh * (KVLEN * HD);
    const __nv_bfloat16* Kl = g_kl + (size_t)bh * (KVLEN * HD);
    const __nv_bfloat16* Vh = g_vh + (size_t)bh * (KVLEN * HD);
    const __nv_bfloat16* Vl = g_vl + (size_t)bh * (KVLEN * HD);

    if (tid < 64) { MR[tid] = -1e30f; LR[tid] = 0.f; }

    // Q tiles -> smem (plain vectorized copy)
#pragma unroll
    for (int i = 0; i < 4; i++) {
        int c = tid + i * 256;                 // 0..1023
        int row = c >> 4, kc = c & 15;
        uint4 v = *(const uint4*)(Qh + (size_t)(qbase + row) * HD + kc * 8);
        *(uint4*)(smraw + AQH + row * 272 + kc * 16) = v;
        v = *(const uint4*)(Ql + (size_t)(qbase + row) * HD + kc * 8);
        *(uint4*)(smraw + AQL + row * 272 + kc * 16) = v;
    }

    int ntile = causal ? (qt + 17) : 32;
    if (ntile > 32) ntile = 32;

    // prologue: issue KV tile 0
    {
        const uint32_t st = sb + AKV;
        const __nv_bfloat16* srcs[4] = {Kh, Kl, Vh, Vl};
#pragma unroll
        for (int t = 0; t < 4; t++)
#pragma unroll
            for (int i = 0; i < 4; i++) {
                int c = tid + i * 256;
                int row = c >> 4, kc = c & 15;
                cpa16(st + t * 17408 + row * 272 + kc * 16,
                      srcs[t] + (size_t)row * HD + kc * 8);
            }
        cpa_commit();
    }

    float oacc[2][4][4];
#pragma unroll
    for (int a = 0; a < 2; a++)
#pragma unroll
        for (int c = 0; c < 4; c++)
#pragma unroll
            for (int e = 0; e < 4; e++) oacc[a][c][e] = 0.f;

    const float scale = 0.08838834764831845f;   // 1/sqrt(128)
    const int roff = KVLEN - TQ;

    for (int kt = 0; kt < ntile; kt++) {
        const int kbase = kt * 64;
        if (kt + 1 < ntile) {
            const uint32_t st = sb + AKV + ((kt + 1) & 1) * AKVSTR;
            const __nv_bfloat16* srcs[4] = {Kh, Kl, Vh, Vl};
            const int nb2 = (kt + 1) * 64;
#pragma unroll
            for (int t = 0; t < 4; t++)
#pragma unroll
                for (int i = 0; i < 4; i++) {
                    int c = tid + i * 256;
                    int row = c >> 4, kc = c & 15;
                    cpa16(st + t * 17408 + row * 272 + kc * 16,
                          srcs[t] + (size_t)(nb2 + row) * HD + kc * 8);
                }
            cpa_commit();
            cpa_wait1();
        } else {
            cpa_wait0();
        }
        __syncthreads();                                   // sync1: KV tile kt ready

        const uint32_t kvst = sb + AKV + (kt & 1) * AKVSTR;

        // ---- S = Q K^T (split, 3 terms) ----
        float sacc[2][2][4];
#pragma unroll
        for (int a = 0; a < 2; a++)
#pragma unroll
            for (int c = 0; c < 2; c++)
#pragma unroll
                for (int e = 0; e < 4; e++) sacc[a][c][e] = 0.f;

        const uint32_t qrow = (uint32_t)(wm * 32 + (lane & 15)) * 272;
        const uint32_t krow = (uint32_t)(wn * 16 + (lane & 15)) * 272;
#pragma unroll
        for (int ks = 0; ks < 8; ks++) {
            const uint32_t koff = ks * 32 + (lane >> 4) * 16;
            uint32_t qa[2][4], qb[2][4], kbf[4], klf[4];
#pragma unroll
            for (int mt = 0; mt < 2; mt++)
                ldm4(qa[mt], sb + AQH + qrow + mt * 16 * 272 + koff);
            ldm4(kbf, kvst + AKHOF + krow + koff);
#pragma unroll
            for (int mt = 0; mt < 2; mt++)
#pragma unroll
                for (int nt = 0; nt < 2; nt++)
                    mma16816(sacc[mt][nt], qa[mt], kbf[nt], kbf[nt + 2]);
            ldm4(klf, kvst + AKLOF + krow + koff);
#pragma unroll
            for (int mt = 0; mt < 2; mt++)
#pragma unroll
                for (int nt = 0; nt < 2; nt++)
                    mma16816(sacc[mt][nt], qa[mt], klf[nt], klf[nt + 2]);
#pragma unroll
            for (int mt = 0; mt < 2; mt++)
                ldm4(qb[mt], sb + AQL + qrow + mt * 16 * 272 + koff);
#pragma unroll
            for (int mt = 0; mt < 2; mt++)
#pragma unroll
                for (int nt = 0; nt < 2; nt++)
                    mma16816(sacc[mt][nt], qb[mt], kbf[nt], kbf[nt + 2]);
        }

        // ---- scale + mask + partial row max ----
#pragma unroll
        for (int mt = 0; mt < 2; mt++)
#pragma unroll
            for (int nt = 0; nt < 2; nt++)
#pragma unroll
                for (int e = 0; e < 4; e++) {
                    int rl = wm * 32 + mt * 16 + (e >> 1) * 8 + (lane >> 2);
                    int cl = wn * 16 + nt * 8 + (lane & 3) * 2 + (e & 1);
                    float v = sacc[mt][nt][e] * scale;
                    if (causal && (kbase + cl) > (qbase + rl + roff)) v = -1e30f;
                    sacc[mt][nt][e] = v;
                }
#pragma unroll
        for (int mt = 0; mt < 2; mt++)
#pragma unroll
            for (int hh = 0; hh < 2; hh++) {
                float m = fmaxf(fmaxf(sacc[mt][0][2 * hh], sacc[mt][0][2 * hh + 1]),
                                fmaxf(sacc[mt][1][2 * hh], sacc[mt][1][2 * hh + 1]));
                m = fmaxf(m, __shfl_xor_sync(0xffffffffu, m, 1));
                m = fmaxf(m, __shfl_xor_sync(0xffffffffu, m, 2));
                if ((lane & 3) == 0)
                    RM[(wm * 32 + mt * 16 + hh * 8 + (lane >> 2)) * 4 + wn] = m;
            }
        __syncthreads();                                   // sync2

        if (tid < 64) {
            float m4 = fmaxf(fmaxf(RM[tid * 4], RM[tid * 4 + 1]),
                             fmaxf(RM[tid * 4 + 2], RM[tid * 4 + 3]));
            float mo = MR[tid];
            float nm = fmaxf(mo, m4);
            MR[tid] = nm; NM[tid] = nm; AR[tid] = __expf(mo - nm);
        }
        __syncthreads();                                   // sync3

        // ---- P = exp(S - m), store hi/lo, partial sums, rescale O ----
#pragma unroll
        for (int mt = 0; mt < 2; mt++)
#pragma unroll
            for (int hh = 0; hh < 2; hh++) {
                int rl = wm * 32 + mt * 16 + hh * 8 + (lane >> 2);
                float nm = NM[rl], al = AR[rl];
                float ps = 0.f;
#pragma unroll
                for (int nt = 0; nt < 2; nt++) {
                    float p0 = __expf(sacc[mt][nt][2 * hh]     - nm);
                    float p1 = __expf(sacc[mt][nt][2 * hh + 1] - nm);
                    ps += p0 + p1;
                    __nv_bfloat16 h0, l0, h1, l1;
                    split2(p0, h0, l0); split2(p1, h1, l1);
                    uint32_t off = rl * 144 + (wn * 16 + nt * 8 + (lane & 3) * 2) * 2;
                    *(__nv_bfloat162*)(smraw + APH + off) = __nv_bfloat162{h0, h1};
                    *(__nv_bfloat162*)(smraw + APL + off) = __nv_bfloat162{l0, l1};
                }
                ps += __shfl_xor_sync(0xffffffffu, ps, 1);
                ps += __shfl_xor_sync(0xffffffffu, ps, 2);
                if ((lane & 3) == 0) RS[rl * 4 + wn] = ps;
#pragma unroll
                for (int nq = 0; nq < 4; nq++) {
                    oacc[mt][nq][2 * hh]     *= al;
                    oacc[mt][nq][2 * hh + 1] *= al;
                }
            }
        __syncthreads();                                   // sync4: P complete

        if (tid < 64)
            LR[tid] = LR[tid] * AR[tid] +
                      (RS[tid * 4] + RS[tid * 4 + 1] + RS[tid * 4 + 2] + RS[tid * 4 + 3]);

        // ---- O += P V (split, 3 terms) ----
        const uint32_t prow = (uint32_t)(wm * 32 + (lane & 15)) * 144;
        const uint32_t vcol = (uint32_t)(wn * 32) * 2 + (lane >> 4) * 16;
#pragma unroll
        for (int ks = 0; ks < 4; ks++) {
            const uint32_t koff = ks * 32 + (lane >> 4) * 16;
            const uint32_t vrow = (uint32_t)(ks * 16 + (lane & 15)) * 272;
            uint32_t pa[2][4], pb[2][4], vbh[2][4], vbl[2][4];
#pragma unroll
            for (int mt = 0; mt < 2; mt++)
                ldm4(pa[mt], sb + APH + prow + mt * 16 * 144 + koff);
#pragma unroll
            for (int np = 0; np < 2; np++)
                ldm4t(vbh[np], kvst + AVHOF + vrow + vcol + np * 32);
#pragma unroll
            for (int mt = 0; mt < 2; mt++)
#pragma unroll
                for (int nq = 0; nq < 4; nq++)
                    mma16816(oacc[mt][nq], pa[mt],
                             vbh[nq >> 1][(nq & 1) * 2], vbh[nq >> 1][(nq & 1) * 2 + 1]);
#pragma unroll
            for (int np = 0; np < 2; np++)
                ldm4t(vbl[np], kvst + AVLOF + vrow + vcol + np * 32);
#pragma unroll
            for (int mt = 0; mt < 2; mt++)
#pragma unroll
                for (int nq = 0; nq < 4; nq++)
                    mma16816(oacc[mt][nq], pa[mt],
                             vbl[nq >> 1][(nq & 1) * 2], vbl[nq >> 1][(nq & 1) * 2 + 1]);
#pragma unroll
            for (int mt = 0; mt < 2; mt++)
                ldm4(pb[mt], sb + APL + prow + mt * 16 * 144 + koff);
#pragma unroll
            for (int mt = 0; mt < 2; mt++)
#pragma unroll
                for (int nq = 0; nq < 4; nq++)
                    mma16816(oacc[mt][nq], pb[mt],
                             vbh[nq >> 1][(nq & 1) * 2], vbh[nq >> 1][(nq & 1) * 2 + 1]);
        }
        __syncthreads();                                   // sync5
    }

    // epilogue: O / l -> g_y[(b,t),(h,d)]
#pragma unroll
    for (int mt = 0; mt < 2; mt++)
#pragma unroll
        for (int hh = 0; hh < 2; hh++) {
            int rl = wm * 32 + mt * 16 + hh * 8 + (lane >> 2);
            float inv = 1.0f / LR[rl];
            float* Yp = g_y + (size_t)(b * TQ + qbase + rl) * D_MODEL + h * HD;
#pragma unroll
            for (int nq = 0; nq < 4; nq++) {
                int col = wn * 32 + nq * 8 + (lane & 3) * 2;
                *(float2*)(Yp + col) = make_float2(oacc[mt][nq][2 * hh] * inv,
                                                   oacc[mt][nq][2 * hh + 1] * inv);
            }
        }
}

// =====================================================================
// launch
// =====================================================================
extern "C" void kernel_launch(void* const* d_in, const int* in_sizes, int n_in,
                              void* d_out, int out_size)
{
    const float* x     = (const float*)d_in[0];
    const float* cosb  = (const float*)d_in[1];
    const float* sinb  = (const float*)d_in[2];
    const float* kxl   = (const float*)d_in[3];
    const float* vxl   = (const float*)d_in[4];
    const float* pos   = (const float*)d_in[5];
    const float* wqkv  = (const float*)d_in[6];
    const float* wproj = (const float*)d_in[7];
    const int*   flag  = (const int*)d_in[8];
    float*       out   = (float*)d_out;

    float *qkv, *y;
    __nv_bfloat16 *ah, *al, *bh, *bl;
    cudaGetSymbolAddress((void**)&qkv, g_qkv);
    cudaGetSymbolAddress((void**)&y,   g_y);
    cudaGetSymbolAddress((void**)&ah,  g_ah);
    cudaGetSymbolAddress((void**)&al,  g_al);
    cudaGetSymbolAddress((void**)&bh,  g_bh);
    cudaGetSymbolAddress((void**)&bl,  g_bl);

    cudaFuncSetAttribute(attn_kernel, cudaFuncAttributeMaxDynamicSharedMemorySize,
                         ATTN_SMEM);
    cudaFuncSetAttribute(gemm_mma, cudaFuncAttributeMaxDynamicSharedMemorySize,
                         GEMM_SMEM);

    const int nA  = MROWS * D_MODEL / 4;
    const int nBq = 3 * D_MODEL * D_MODEL / 4;
    const int nBp = D_MODEL * D_MODEL / 4;

    // 1) split x, w_qkv; qkv = x @ w_qkv^T
    split_bf16_kernel<<<(nA + 255) / 256, 256>>>(x, ah, al, nA);
    split_bf16_kernel<<<(nBq + 255) / 256, 256>>>(wqkv, bh, bl, nBq);
    gemm_mma<<<dim3(3 * D_MODEL / 128, MROWS / 128), 256, GEMM_SMEM>>>(
        ah, al, bh, bl, qkv, MROWS, 3 * D_MODEL, D_MODEL);

    // 2) XL prep + RoPE scatter (bf16 hi/lo)
    xl_prep<<<(BATCH * XLLEN * D_MODEL / 2) / 256, 256>>>(kxl, vxl, pos);
    rope_split<<<(BATCH * TQ * NHEADS * 64) / 256, 256>>>(cosb, sinb);

    // 3) flash attention -> g_y
    attn_kernel<<<dim3(TQ / 64, BATCH * NHEADS), 256, ATTN_SMEM>>>(flag);

    // 4) split y, w_proj; out = y @ w_proj^T
    split_bf16_kernel<<<(nA + 255) / 256, 256>>>(y, ah, al, nA);
    split_bf16_kernel<<<(nBp + 255) / 256, 256>>>(wproj, bh, bl, nBp);
    gemm_mma<<<dim3(D_MODEL / 128, MROWS / 128), 256, GEMM_SMEM>>>(
        ah, al, bh, bl, out, MROWS, D_MODEL, D_MODEL);
}

// round 5
// speedup vs baseline: 4.9184x; 2.2466x over previous
#include <cuda_runtime.h>
#include <cuda_fp16.h>
#include <cstdint>

#define D_MODEL 2048
#define NHEADS  16
#define HD      128
#define BATCH   2
#define TQ      1024
#define XLLEN   1024
#define KVLEN   2048
#define MROWS   (BATCH * TQ)    // 2048

// ---------------- scratch (device globals) ----------------
__device__ float g_qkv[(size_t)MROWS * 3 * D_MODEL];
__device__ float g_y  [(size_t)MROWS * D_MODEL];
__device__ __half g_qh[(size_t)BATCH * NHEADS * TQ * HD];
__device__ __half g_kh[(size_t)BATCH * NHEADS * KVLEN * HD];
__device__ __half g_vh[(size_t)BATCH * NHEADS * KVLEN * HD];
__device__ __half g_ah[(size_t)MROWS * D_MODEL];
__device__ __half g_bh[(size_t)3 * D_MODEL * D_MODEL];

// ======================= PTX helpers =======================
__device__ __forceinline__ uint32_t smem_u32(const void* p) {
    uint32_t a;
    asm("{ .reg .u64 t; cvta.to.shared.u64 t, %1; cvt.u32.u64 %0, t; }" : "=r"(a) : "l"(p));
    return a;
}
__device__ __forceinline__ void ldm4(uint32_t* r, uint32_t a) {
    asm volatile("ldmatrix.sync.aligned.m8n8.x4.shared.b16 {%0,%1,%2,%3}, [%4];"
                 : "=r"(r[0]), "=r"(r[1]), "=r"(r[2]), "=r"(r[3]) : "r"(a));
}
__device__ __forceinline__ void ldm4t(uint32_t* r, uint32_t a) {
    asm volatile("ldmatrix.sync.aligned.m8n8.x4.trans.shared.b16 {%0,%1,%2,%3}, [%4];"
                 : "=r"(r[0]), "=r"(r[1]), "=r"(r[2]), "=r"(r[3]) : "r"(a));
}
__device__ __forceinline__ void mma16816(float* d, const uint32_t* a, uint32_t b0, uint32_t b1) {
    asm volatile("mma.sync.aligned.m16n8k16.row.col.f32.f16.f16.f32 "
                 "{%0,%1,%2,%3}, {%4,%5,%6,%7}, {%8,%9}, {%0,%1,%2,%3};"
                 : "+f"(d[0]), "+f"(d[1]), "+f"(d[2]), "+f"(d[3])
                 : "r"(a[0]), "r"(a[1]), "r"(a[2]), "r"(a[3]), "r"(b0), "r"(b1));
}
__device__ __forceinline__ void cpa16(uint32_t dst, const void* src) {
    asm volatile("cp.async.cg.shared.global [%0], [%1], 16;" :: "r"(dst), "l"(src));
}
__device__ __forceinline__ void cpa_commit() { asm volatile("cp.async.commit_group;" ::: "memory"); }
__device__ __forceinline__ void cpa_wait2()  { asm volatile("cp.async.wait_group 2;" ::: "memory"); }
__device__ __forceinline__ void cpa_wait1()  { asm volatile("cp.async.wait_group 1;" ::: "memory"); }
__device__ __forceinline__ void cpa_wait0()  { asm volatile("cp.async.wait_group 0;" ::: "memory"); }

// =====================================================================
// fp32 -> fp16 convert
// =====================================================================
__global__ void tohalf_kernel(const float* __restrict__ src, __half* __restrict__ dst, int n4)
{
    int i = blockIdx.x * blockDim.x + threadIdx.x;
    if (i >= n4) return;
    float4 v = ((const float4*)src)[i];
    __half h[4] = {__float2half_rn(v.x), __float2half_rn(v.y),
                   __float2half_rn(v.z), __float2half_rn(v.w)};
    *(uint2*)(dst + (size_t)i * 4) = *(uint2*)h;
}

// =====================================================================
// fp16 mma.sync NT GEMM: C[M,N] = A[M,K]*B[N,K]^T, fp32 out.
// 128x128 tile, BK=32, 8 warps (warp tile 64x32), cp.async 4-stage.
// smem rows: 64B data + 16B pad (80B stride, conflict-free ldmatrix).
// =====================================================================
#define GTILE_B  10240            // 128 rows x 80B
#define GSTG_B   (2 * GTILE_B)    // A + B
#define GEMM_SMEM (4 * GSTG_B)    // 81920

__global__ __launch_bounds__(256) void gemm_mma(
    const __half* __restrict__ A, const __half* __restrict__ B,
    float* __restrict__ C, int M, int N, int K)
{
    extern __shared__ __align__(16) char smraw[];
    const uint32_t sb = smem_u32(smraw);
    const int tid = threadIdx.x, wid = tid >> 5, lane = tid & 31;
    const int wm = wid & 1, wn = wid >> 1;
    const int mb = blockIdx.y * 128, nb = blockIdx.x * 128;

    const __half* srcs[2] = { A + (size_t)mb * K, B + (size_t)nb * K };
    const int NKB = K >> 5;

    // prologue: issue stages 0..2
#pragma unroll
    for (int s = 0; s < 3; s++) {
        const uint32_t st = sb + s * GSTG_B;
        const int ko = s * 32;
#pragma unroll
        for (int t = 0; t < 2; t++) {
            const __half* g = srcs[t];
#pragma unroll
            for (int i = 0; i < 2; i++) {
                int c = tid + i * 256;
                int row = c >> 2, kc = c & 3;
                cpa16(st + t * GTILE_B + row * 80 + kc * 16,
                      g + (size_t)row * K + ko + kc * 8);
            }
        }
        cpa_commit();
    }

    float acc[4][4][4];
#pragma unroll
    for (int a = 0; a < 4; a++)
#pragma unroll
        for (int b = 0; b < 4; b++)
#pragma unroll
            for (int e = 0; e < 4; e++) acc[a][b][e] = 0.f;

    for (int kb = 0; kb < NKB; kb++) {
        if (kb + 2 < NKB) cpa_wait2();
        else if (kb + 1 < NKB) cpa_wait1();
        else cpa_wait0();
        __syncthreads();

        if (kb + 3 < NKB) {
            const uint32_t st = sb + ((kb + 3) & 3) * GSTG_B;
            const int ko = (kb + 3) * 32;
#pragma unroll
            for (int t = 0; t < 2; t++) {
                const __half* g = srcs[t];
#pragma unroll
                for (int i = 0; i < 2; i++) {
                    int c = tid + i * 256;
                    int row = c >> 2, kc = c & 3;
                    cpa16(st + t * GTILE_B + row * 80 + kc * 16,
                          g + (size_t)row * K + ko + kc * 8);
                }
            }
            cpa_commit();
        }

        const uint32_t st = sb + (kb & 3) * GSTG_B;
        const uint32_t arow = (uint32_t)(wm * 64 + (lane & 15)) * 80;
        const uint32_t brow = (uint32_t)(wn * 32 + (lane & 15)) * 80;
#pragma unroll
        for (int ks = 0; ks < 2; ks++) {
            const uint32_t koff = ks * 32 + (lane >> 4) * 16;
            uint32_t Af[4][4], Bf[2][4];
#pragma unroll
            for (int mt = 0; mt < 4; mt++)
                ldm4(Af[mt], st + arow + mt * 16 * 80 + koff);
#pragma unroll
            for (int np = 0; np < 2; np++)
                ldm4(Bf[np], st + GTILE_B + brow + np * 16 * 80 + koff);
#pragma unroll
            for (int mt = 0; mt < 4; mt++)
#pragma unroll
                for (int nt = 0; nt < 4; nt++)
                    mma16816(acc[mt][nt], Af[mt], Bf[nt >> 1][nt & 1], Bf[nt >> 1][(nt & 1) + 2]);
        }
    }

    // epilogue
#pragma unroll
    for (int mt = 0; mt < 4; mt++) {
        int row0 = mb + wm * 64 + mt * 16 + (lane >> 2);
#pragma unroll
        for (int nt = 0; nt < 4; nt++) {
            int col = nb + wn * 32 + nt * 8 + (lane & 3) * 2;
            *(float2*)&C[(size_t)row0 * N + col]       = make_float2(acc[mt][nt][0], acc[mt][nt][1]);
            *(float2*)&C[(size_t)(row0 + 8) * N + col] = make_float2(acc[mt][nt][2], acc[mt][nt][3]);
        }
    }
}

// =====================================================================
// XL prep: k_full[:XL] = fp16(k_xl + pos_emb), v_full[:XL] = fp16(v_xl)
// =====================================================================
__global__ void xl_prep(const float* __restrict__ kxl, const float* __restrict__ vxl,
                        const float* __restrict__ pos)
{
    int idx = blockIdx.x * blockDim.x + threadIdx.x;   // B*XL*D/2
    int c2 = idx & 1023;
    int t  = (idx >> 10) & 1023;
    int b  = idx >> 20;
    int c = c2 * 2;
    int h = c >> 7, d = c & 127;
    size_t src = ((size_t)(b * XLLEN + t)) * D_MODEL + c;
    float2 kv = *(const float2*)(kxl + src);
    float2 pv = *(const float2*)(pos + (size_t)t * D_MODEL + c);
    float2 vv = *(const float2*)(vxl + src);
    size_t dst = ((size_t)((b * NHEADS + h) * KVLEN + t)) * HD + d;
    *(__half2*)&g_kh[dst] = __half2{__float2half_rn(kv.x + pv.x), __float2half_rn(kv.y + pv.y)};
    *(__half2*)&g_vh[dst] = __half2{__float2half_rn(vv.x), __float2half_rn(vv.y)};
}

// =====================================================================
// RoPE + split qkv -> fp16 q, k_full[XL:], v_full[XL:]
// =====================================================================
__global__ void rope_split(const float* __restrict__ cosb, const float* __restrict__ sinb)
{
    int idx = blockIdx.x * blockDim.x + threadIdx.x;   // 2,097,152
    int dp = idx & 63;
    int h  = (idx >> 6) & 15;
    int t  = (idx >> 10) & 1023;
    int b  = idx >> 20;
    int m  = b * TQ + t;

    const float* base = g_qkv + (size_t)m * (3 * D_MODEL) + h * HD + 2 * dp;
    float c = cosb[t * 64 + dp];
    float s = sinb[t * 64 + dp];
    float2 qv = *(const float2*)(base);
    float2 kv = *(const float2*)(base + D_MODEL);
    float2 vv = *(const float2*)(base + 2 * D_MODEL);
    float q0 = qv.x * c - qv.y * s, q1 = qv.x * s + qv.y * c;
    float k0 = kv.x * c - kv.y * s, k1 = kv.x * s + kv.y * c;

    size_t bh = (size_t)(b * NHEADS + h);
    size_t qd = (bh * TQ + t) * HD + 2 * dp;
    size_t kd = (bh * KVLEN + XLLEN + t) * HD + 2 * dp;
    *(__half2*)&g_qh[qd] = __half2{__float2half_rn(q0), __float2half_rn(q1)};
    *(__half2*)&g_kh[kd] = __half2{__float2half_rn(k0), __float2half_rn(k1)};
    *(__half2*)&g_vh[kd] = __half2{__float2half_rn(vv.x), __float2half_rn(vv.y)};
}

// =====================================================================
// Flash attention fp16 mma.sync: BQ=64, BK=64, D=128, 8 warps.
// Q/K/V tiles: [64][136] fp16 (272B rows); P: [64][72] (144B rows).
// K/V double-buffered via cp.async.
// =====================================================================
#define AQ   0
#define AKV  17408
#define AKVSTR 34816
#define AVOF 17408
#define AP   87040
#define ARM  96256
#define ARS  97280
#define AMR  98304
#define ALR  98560
#define ANM  98816
#define AAR  99072
#define ATTN_SMEM 99328

__global__ __launch_bounds__(256) void attn_kernel(const int* __restrict__ flag)
{
    extern __shared__ __align__(16) char smraw[];
    const uint32_t sb = smem_u32(smraw);
    float* RM = (float*)(smraw + ARM);
    float* RS = (float*)(smraw + ARS);
    float* MR = (float*)(smraw + AMR);
    float* LR = (float*)(smraw + ALR);
    float* NM = (float*)(smraw + ANM);
    float* AR = (float*)(smraw + AAR);

    const int tid = threadIdx.x, wid = tid >> 5, lane = tid & 31;
    const int wm = wid & 1, wn = wid >> 1;
    const int qt = blockIdx.x, bh = blockIdx.y;
    const int b = bh >> 4, h = bh & 15;
    const int qbase = qt * 64;
    const int causal = *flag;

    const __half* Qh = g_qh + (size_t)bh * (TQ * HD);
    const __half* Kh = g_kh + (size_t)bh * (KVLEN * HD);
    const __half* Vh = g_vh + (size_t)bh * (KVLEN * HD);

    if (tid < 64) { MR[tid] = -1e30f; LR[tid] = 0.f; }

    // Q tile -> smem
#pragma unroll
    for (int i = 0; i < 4; i++) {
        int c = tid + i * 256;
        int row = c >> 4, kc = c & 15;
        uint4 v = *(const uint4*)(Qh + (size_t)(qbase + row) * HD + kc * 8);
        *(uint4*)(smraw + AQ + row * 272 + kc * 16) = v;
    }

    int ntile = causal ? (qt + 17) : 32;
    if (ntile > 32) ntile = 32;

    // prologue: KV tile 0
    {
        const uint32_t st = sb + AKV;
        const __half* srcs[2] = {Kh, Vh};
#pragma unroll
        for (int t = 0; t < 2; t++)
#pragma unroll
            for (int i = 0; i < 4; i++) {
                int c = tid + i * 256;
                int row = c >> 4, kc = c & 15;
                cpa16(st + t * 17408 + row * 272 + kc * 16,
                      srcs[t] + (size_t)row * HD + kc * 8);
            }
        cpa_commit();
    }

    float oacc[2][4][4];
#pragma unroll
    for (int a = 0; a < 2; a++)
#pragma unroll
        for (int c = 0; c < 4; c++)
#pragma unroll
            for (int e = 0; e < 4; e++) oacc[a][c][e] = 0.f;

    const float scale = 0.08838834764831845f;   // 1/sqrt(128)
    const int roff = KVLEN - TQ;

    for (int kt = 0; kt < ntile; kt++) {
        const int kbase = kt * 64;
        if (kt + 1 < ntile) {
            const uint32_t st = sb + AKV + ((kt + 1) & 1) * AKVSTR;
            const __half* srcs[2] = {Kh, Vh};
            const int nb2 = (kt + 1) * 64;
#pragma unroll
            for (int t = 0; t < 2; t++)
#pragma unroll
                for (int i = 0; i < 4; i++) {
                    int c = tid + i * 256;
                    int row = c >> 4, kc = c & 15;
                    cpa16(st + t * 17408 + row * 272 + kc * 16,
                          srcs[t] + (size_t)(nb2 + row) * HD + kc * 8);
                }
            cpa_commit();
            cpa_wait1();
        } else {
            cpa_wait0();
        }
        __syncthreads();                                   // KV tile kt ready

        const uint32_t kvst = sb + AKV + (kt & 1) * AKVSTR;

        // ---- S = Q K^T ----
        float sacc[2][2][4];
#pragma unroll
        for (int a = 0; a < 2; a++)
#pragma unroll
            for (int c = 0; c < 2; c++)
#pragma unroll
                for (int e = 0; e < 4; e++) sacc[a][c][e] = 0.f;

        const uint32_t qrow = (uint32_t)(wm * 32 + (lane & 15)) * 272;
        const uint32_t krow = (uint32_t)(wn * 16 + (lane & 15)) * 272;
#pragma unroll
        for (int ks = 0; ks < 8; ks++) {
            const uint32_t koff = ks * 32 + (lane >> 4) * 16;
            uint32_t qa[2][4], kf[4];
#pragma unroll
            for (int mt = 0; mt < 2; mt++)
                ldm4(qa[mt], sb + AQ + qrow + mt * 16 * 272 + koff);
            ldm4(kf, kvst + krow + koff);
#pragma unroll
            for (int mt = 0; mt < 2; mt++)
#pragma unroll
                for (int nt = 0; nt < 2; nt++)
                    mma16816(sacc[mt][nt], qa[mt], kf[nt], kf[nt + 2]);
        }

        // ---- scale + mask + partial row max ----
#pragma unroll
        for (int mt = 0; mt < 2; mt++)
#pragma unroll
            for (int nt = 0; nt < 2; nt++)
#pragma unroll
                for (int e = 0; e < 4; e++) {
                    int rl = wm * 32 + mt * 16 + (e >> 1) * 8 + (lane >> 2);
                    int cl = wn * 16 + nt * 8 + (lane & 3) * 2 + (e & 1);
                    float v = sacc[mt][nt][e] * scale;
                    if (causal && (kbase + cl) > (qbase + rl + roff)) v = -1e30f;
                    sacc[mt][nt][e] = v;
                }
#pragma unroll
        for (int mt = 0; mt < 2; mt++)
#pragma unroll
            for (int hh = 0; hh < 2; hh++) {
                float m = fmaxf(fmaxf(sacc[mt][0][2 * hh], sacc[mt][0][2 * hh + 1]),
                                fmaxf(sacc[mt][1][2 * hh], sacc[mt][1][2 * hh + 1]));
                m = fmaxf(m, __shfl_xor_sync(0xffffffffu, m, 1));
                m = fmaxf(m, __shfl_xor_sync(0xffffffffu, m, 2));
                if ((lane & 3) == 0)
                    RM[(wm * 32 + mt * 16 + hh * 8 + (lane >> 2)) * 4 + wn] = m;
            }
        __syncthreads();

        if (tid < 64) {
            float m4 = fmaxf(fmaxf(RM[tid * 4], RM[tid * 4 + 1]),
                             fmaxf(RM[tid * 4 + 2], RM[tid * 4 + 3]));
            float mo = MR[tid];
            float nm = fmaxf(mo, m4);
            MR[tid] = nm; NM[tid] = nm; AR[tid] = __expf(mo - nm);
        }
        __syncthreads();

        // ---- P = exp(S - m) fp16, partial sums, rescale O ----
#pragma unroll
        for (int mt = 0; mt < 2; mt++)
#pragma unroll
            for (int hh = 0; hh < 2; hh++) {
                int rl = wm * 32 + mt * 16 + hh * 8 + (lane >> 2);
                float nm = NM[rl], al = AR[rl];
                float ps = 0.f;
#pragma unroll
                for (int nt = 0; nt < 2; nt++) {
                    float p0 = __expf(sacc[mt][nt][2 * hh]     - nm);
                    float p1 = __expf(sacc[mt][nt][2 * hh + 1] - nm);
                    ps += p0 + p1;
                    uint32_t off = rl * 144 + (wn * 16 + nt * 8 + (lane & 3) * 2) * 2;
                    *(__half2*)(smraw + AP + off) =
                        __half2{__float2half_rn(p0), __float2half_rn(p1)};
                }
                ps += __shfl_xor_sync(0xffffffffu, ps, 1);
                ps += __shfl_xor_sync(0xffffffffu, ps, 2);
                if ((lane & 3) == 0) RS[rl * 4 + wn] = ps;
#pragma unroll
                for (int nq = 0; nq < 4; nq++) {
                    oacc[mt][nq][2 * hh]     *= al;
                    oacc[mt][nq][2 * hh + 1] *= al;
                }
            }
        __syncthreads();                                   // P complete

        if (tid < 64)
            LR[tid] = LR[tid] * AR[tid] +
                      (RS[tid * 4] + RS[tid * 4 + 1] + RS[tid * 4 + 2] + RS[tid * 4 + 3]);

        // ---- O += P V ----
        const uint32_t prow = (uint32_t)(wm * 32 + (lane & 15)) * 144;
        const uint32_t vcol = (uint32_t)(wn * 32) * 2 + (lane >> 4) * 16;
#pragma unroll
        for (int ks = 0; ks < 4; ks++) {
            const uint32_t koff = ks * 32 + (lane >> 4) * 16;
            const uint32_t vrow = (uint32_t)(ks * 16 + (lane & 15)) * 272;
            uint32_t pa[2][4], vb[2][4];
#pragma unroll
            for (int mt = 0; mt < 2; mt++)
                ldm4(pa[mt], sb + AP + prow + mt * 16 * 144 + koff);
#pragma unroll
            for (int np = 0; np < 2; np++)
                ldm4t(vb[np], kvst + AVOF + vrow + vcol + np * 32);
#pragma unroll
            for (int mt = 0; mt < 2; mt++)
#pragma unroll
                for (int nq = 0; nq < 4; nq++)
                    mma16816(oacc[mt][nq], pa[mt],
                             vb[nq >> 1][(nq & 1) * 2], vb[nq >> 1][(nq & 1) * 2 + 1]);
        }
        __syncthreads();
    }

    // epilogue: O / l -> g_y[(b,t),(h,d)]
#pragma unroll
    for (int mt = 0; mt < 2; mt++)
#pragma unroll
        for (int hh = 0; hh < 2; hh++) {
            int rl = wm * 32 + mt * 16 + hh * 8 + (lane >> 2);
            float inv = 1.0f / LR[rl];
            float* Yp = g_y + (size_t)(b * TQ + qbase + rl) * D_MODEL + h * HD;
#pragma unroll
            for (int nq = 0; nq < 4; nq++) {
                int col = wn * 32 + nq * 8 + (lane & 3) * 2;
                *(float2*)(Yp + col) = make_float2(oacc[mt][nq][2 * hh] * inv,
                                                   oacc[mt][nq][2 * hh + 1] * inv);
            }
        }
}

// =====================================================================
// launch
// =====================================================================
extern "C" void kernel_launch(void* const* d_in, const int* in_sizes, int n_in,
                              void* d_out, int out_size)
{
    const float* x     = (const float*)d_in[0];
    const float* cosb  = (const float*)d_in[1];
    const float* sinb  = (const float*)d_in[2];
    const float* kxl   = (const float*)d_in[3];
    const float* vxl   = (const float*)d_in[4];
    const float* pos   = (const float*)d_in[5];
    const float* wqkv  = (const float*)d_in[6];
    const float* wproj = (const float*)d_in[7];
    const int*   flag  = (const int*)d_in[8];
    float*       out   = (float*)d_out;

    float *qkv, *y;
    __half *ah, *bh;
    cudaGetSymbolAddress((void**)&qkv, g_qkv);
    cudaGetSymbolAddress((void**)&y,   g_y);
    cudaGetSymbolAddress((void**)&ah,  g_ah);
    cudaGetSymbolAddress((void**)&bh,  g_bh);

    cudaFuncSetAttribute(attn_kernel, cudaFuncAttributeMaxDynamicSharedMemorySize,
                         ATTN_SMEM);
    cudaFuncSetAttribute(gemm_mma, cudaFuncAttributeMaxDynamicSharedMemorySize,
                         GEMM_SMEM);

    const int nA  = MROWS * D_MODEL / 4;
    const int nBq = 3 * D_MODEL * D_MODEL / 4;
    const int nBp = D_MODEL * D_MODEL / 4;

    // 1) convert x, w_qkv; qkv = x @ w_qkv^T
    tohalf_kernel<<<(nA + 255) / 256, 256>>>(x, ah, nA);
    tohalf_kernel<<<(nBq + 255) / 256, 256>>>(wqkv, bh, nBq);
    gemm_mma<<<dim3(3 * D_MODEL / 128, MROWS / 128), 256, GEMM_SMEM>>>(
        ah, bh, qkv, MROWS, 3 * D_MODEL, D_MODEL);

    // 2) XL prep + RoPE scatter (fp16)
    xl_prep<<<(BATCH * XLLEN * D_MODEL / 2) / 256, 256>>>(kxl, vxl, pos);
    rope_split<<<(BATCH * TQ * NHEADS * 64) / 256, 256>>>(cosb, sinb);

    // 3) flash attention -> g_y
    attn_kernel<<<dim3(TQ / 64, BATCH * NHEADS), 256, ATTN_SMEM>>>(flag);

    // 4) convert y, w_proj; out = y @ w_proj^T
    tohalf_kernel<<<(nA + 255) / 256, 256>>>(y, ah, nA);
    tohalf_kernel<<<(nBp + 255) / 256, 256>>>(wproj, bh, nBp);
    gemm_mma<<<dim3(D_MODEL / 128, MROWS / 128), 256, GEMM_SMEM>>>(
        ah, bh, out, MROWS, D_MODEL, D_MODEL);
}

// round 6
// speedup vs baseline: 5.4812x; 1.1144x over previous
#include <cuda_runtime.h>
#include <cuda_fp16.h>
#include <cstdint>

#define D_MODEL 2048
#define NHEADS  16
#define HD      128
#define BATCH   2
#define TQ      1024
#define XLLEN   1024
#define KVLEN   2048
#define MROWS   (BATCH * TQ)    // 2048

// ---------------- scratch (device globals) ----------------
__device__ float  g_qkv[(size_t)MROWS * 3 * D_MODEL];
__device__ __half g_yh [(size_t)MROWS * D_MODEL];
__device__ __half g_qh [(size_t)BATCH * NHEADS * TQ * HD];
__device__ __half g_kh [(size_t)BATCH * NHEADS * KVLEN * HD];
__device__ __half g_vh [(size_t)BATCH * NHEADS * KVLEN * HD];
__device__ __half g_ah [(size_t)MROWS * D_MODEL];
__device__ __half g_bh [(size_t)3 * D_MODEL * D_MODEL];

// ======================= PTX helpers =======================
__device__ __forceinline__ uint32_t smem_u32(const void* p) {
    uint32_t a;
    asm("{ .reg .u64 t; cvta.to.shared.u64 t, %1; cvt.u32.u64 %0, t; }" : "=r"(a) : "l"(p));
    return a;
}
__device__ __forceinline__ void ldm4(uint32_t* r, uint32_t a) {
    asm volatile("ldmatrix.sync.aligned.m8n8.x4.shared.b16 {%0,%1,%2,%3}, [%4];"
                 : "=r"(r[0]), "=r"(r[1]), "=r"(r[2]), "=r"(r[3]) : "r"(a));
}
__device__ __forceinline__ void ldm4t(uint32_t* r, uint32_t a) {
    asm volatile("ldmatrix.sync.aligned.m8n8.x4.trans.shared.b16 {%0,%1,%2,%3}, [%4];"
                 : "=r"(r[0]), "=r"(r[1]), "=r"(r[2]), "=r"(r[3]) : "r"(a));
}
__device__ __forceinline__ void mma16816(float* d, const uint32_t* a, uint32_t b0, uint32_t b1) {
    asm volatile("mma.sync.aligned.m16n8k16.row.col.f32.f16.f16.f32 "
                 "{%0,%1,%2,%3}, {%4,%5,%6,%7}, {%8,%9}, {%0,%1,%2,%3};"
                 : "+f"(d[0]), "+f"(d[1]), "+f"(d[2]), "+f"(d[3])
                 : "r"(a[0]), "r"(a[1]), "r"(a[2]), "r"(a[3]), "r"(b0), "r"(b1));
}
__device__ __forceinline__ void cpa16(uint32_t dst, const void* src) {
    asm volatile("cp.async.cg.shared.global [%0], [%1], 16;" :: "r"(dst), "l"(src));
}
__device__ __forceinline__ void cpa_commit() { asm volatile("cp.async.commit_group;" ::: "memory"); }
__device__ __forceinline__ void cpa_wait1()  { asm volatile("cp.async.wait_group 1;" ::: "memory"); }
__device__ __forceinline__ void cpa_wait0()  { asm volatile("cp.async.wait_group 0;" ::: "memory"); }
__device__ __forceinline__ uint32_t packh2(float a, float b) {
    __half2 t = __floats2half2_rn(a, b);
    return *(uint32_t*)&t;
}

// =====================================================================
// fp32 -> fp16 convert
// =====================================================================
__global__ void tohalf_kernel(const float* __restrict__ src, __half* __restrict__ dst, int n4)
{
    int i = blockIdx.x * blockDim.x + threadIdx.x;
    if (i >= n4) return;
    float4 v = ((const float4*)src)[i];
    __half h[4] = {__float2half_rn(v.x), __float2half_rn(v.y),
                   __float2half_rn(v.z), __float2half_rn(v.w)};
    *(uint2*)(dst + (size_t)i * 4) = *(uint2*)h;
}

// =====================================================================
// fp16 mma.sync NT GEMM: C[M,N] = A[M,K]*B[N,K]^T, fp32 out.
// 256x128 CTA tile, BK=32, 8 warps (warp tile 64x64), 3-stage cp.async.
// =====================================================================
#define GA_B   20480              // 256 rows x 80B
#define GB_B   10240              // 128 rows x 80B
#define GSTG_B (GA_B + GB_B)      // 30720
#define GEMM_SMEM (3 * GSTG_B)    // 92160

__global__ __launch_bounds__(256) void gemm_mma(
    const __half* __restrict__ A, const __half* __restrict__ B,
    float* __restrict__ C, int M, int N, int K)
{
    extern __shared__ __align__(16) char smraw[];
    const uint32_t sb = smem_u32(smraw);
    const int tid = threadIdx.x, wid = tid >> 5, lane = tid & 31;
    const int wm = wid & 3, wn = wid >> 2;
    const int mb = blockIdx.y * 256, nb = blockIdx.x * 128;

    const __half* Asrc = A + (size_t)mb * K;
    const __half* Bsrc = B + (size_t)nb * K;
    const int NKB = K >> 5;

    // prologue: stages 0, 1
#pragma unroll
    for (int s = 0; s < 2; s++) {
        const uint32_t st = sb + s * GSTG_B;
        const int ko = s * 32;
#pragma unroll
        for (int i = 0; i < 4; i++) {
            int c = tid + i * 256;
            int row = c >> 2, kc = c & 3;
            cpa16(st + row * 80 + kc * 16, Asrc + (size_t)row * K + ko + kc * 8);
        }
#pragma unroll
        for (int i = 0; i < 2; i++) {
            int c = tid + i * 256;
            int row = c >> 2, kc = c & 3;
            cpa16(st + GA_B + row * 80 + kc * 16, Bsrc + (size_t)row * K + ko + kc * 8);
        }
        cpa_commit();
    }

    float acc[4][8][4];
#pragma unroll
    for (int a = 0; a < 4; a++)
#pragma unroll
        for (int b = 0; b < 8; b++)
#pragma unroll
            for (int e = 0; e < 4; e++) acc[a][b][e] = 0.f;

    for (int kb = 0; kb < NKB; kb++) {
        if (kb + 1 < NKB) cpa_wait1(); else cpa_wait0();
        __syncthreads();

        if (kb + 2 < NKB) {
            const uint32_t st = sb + ((kb + 2) % 3) * GSTG_B;
            const int ko = (kb + 2) * 32;
#pragma unroll
            for (int i = 0; i < 4; i++) {
                int c = tid + i * 256;
                int row = c >> 2, kc = c & 3;
                cpa16(st + row * 80 + kc * 16, Asrc + (size_t)row * K + ko + kc * 8);
            }
#pragma unroll
            for (int i = 0; i < 2; i++) {
                int c = tid + i * 256;
                int row = c >> 2, kc = c & 3;
                cpa16(st + GA_B + row * 80 + kc * 16, Bsrc + (size_t)row * K + ko + kc * 8);
            }
            cpa_commit();
        }

        const uint32_t st = sb + (kb % 3) * GSTG_B;
        const uint32_t arow = (uint32_t)(wm * 64 + (lane & 15)) * 80;
        const uint32_t brow = (uint32_t)(wn * 64 + (lane & 15)) * 80;
#pragma unroll
        for (int ks = 0; ks < 2; ks++) {
            const uint32_t koff = ks * 32 + (lane >> 4) * 16;
            uint32_t Af[4][4], Bf[4][4];
#pragma unroll
            for (int mt = 0; mt < 4; mt++)
                ldm4(Af[mt], st + arow + mt * 16 * 80 + koff);
#pragma unroll
            for (int np = 0; np < 4; np++)
                ldm4(Bf[np], st + GA_B + brow + np * 16 * 80 + koff);
#pragma unroll
            for (int mt = 0; mt < 4; mt++)
#pragma unroll
                for (int nt = 0; nt < 8; nt++)
                    mma16816(acc[mt][nt], Af[mt], Bf[nt >> 1][nt & 1], Bf[nt >> 1][(nt & 1) + 2]);
        }
    }

    // epilogue
#pragma unroll
    for (int mt = 0; mt < 4; mt++) {
        int row0 = mb + wm * 64 + mt * 16 + (lane >> 2);
#pragma unroll
        for (int nt = 0; nt < 8; nt++) {
            int col = nb + wn * 64 + nt * 8 + (lane & 3) * 2;
            *(float2*)&C[(size_t)row0 * N + col]       = make_float2(acc[mt][nt][0], acc[mt][nt][1]);
            *(float2*)&C[(size_t)(row0 + 8) * N + col] = make_float2(acc[mt][nt][2], acc[mt][nt][3]);
        }
    }
}

// =====================================================================
// XL prep: k_full[:XL] = fp16(k_xl + pos_emb), v_full[:XL] = fp16(v_xl)
// =====================================================================
__global__ void xl_prep(const float* __restrict__ kxl, const float* __restrict__ vxl,
                        const float* __restrict__ pos)
{
    int idx = blockIdx.x * blockDim.x + threadIdx.x;
    int c2 = idx & 1023;
    int t  = (idx >> 10) & 1023;
    int b  = idx >> 20;
    int c = c2 * 2;
    int h = c >> 7, d = c & 127;
    size_t src = ((size_t)(b * XLLEN + t)) * D_MODEL + c;
    float2 kv = *(const float2*)(kxl + src);
    float2 pv = *(const float2*)(pos + (size_t)t * D_MODEL + c);
    float2 vv = *(const float2*)(vxl + src);
    size_t dst = ((size_t)((b * NHEADS + h) * KVLEN + t)) * HD + d;
    *(__half2*)&g_kh[dst] = __half2{__float2half_rn(kv.x + pv.x), __float2half_rn(kv.y + pv.y)};
    *(__half2*)&g_vh[dst] = __half2{__float2half_rn(vv.x), __float2half_rn(vv.y)};
}

// =====================================================================
// RoPE + split qkv -> fp16 q, k_full[XL:], v_full[XL:]
// =====================================================================
__global__ void rope_split(const float* __restrict__ cosb, const float* __restrict__ sinb)
{
    int idx = blockIdx.x * blockDim.x + threadIdx.x;
    int dp = idx & 63;
    int h  = (idx >> 6) & 15;
    int t  = (idx >> 10) & 1023;
    int b  = idx >> 20;
    int m  = b * TQ + t;

    const float* base = g_qkv + (size_t)m * (3 * D_MODEL) + h * HD + 2 * dp;
    float c = cosb[t * 64 + dp];
    float s = sinb[t * 64 + dp];
    float2 qv = *(const float2*)(base);
    float2 kv = *(const float2*)(base + D_MODEL);
    float2 vv = *(const float2*)(base + 2 * D_MODEL);
    float q0 = qv.x * c - qv.y * s, q1 = qv.x * s + qv.y * c;
    float k0 = kv.x * c - kv.y * s, k1 = kv.x * s + kv.y * c;

    size_t bh = (size_t)(b * NHEADS + h);
    size_t qd = (bh * TQ + t) * HD + 2 * dp;
    size_t kd = (bh * KVLEN + XLLEN + t) * HD + 2 * dp;
    *(__half2*)&g_qh[qd] = __half2{__float2half_rn(q0), __float2half_rn(q1)};
    *(__half2*)&g_kh[kd] = __half2{__float2half_rn(k0), __float2half_rn(k1)};
    *(__half2*)&g_vh[kd] = __half2{__float2half_rn(vv.x), __float2half_rn(vv.y)};
}

// =====================================================================
// Flash attention FA2-style: BQ=128, BK=64, D=128, 8 warps.
// Each warp owns 16 Q rows; softmax stats in registers (quad shfl);
// P fed to PV mma directly from S accumulator registers (no smem P).
// Q frags held in registers across the whole KV loop.
// =====================================================================
#define AQSZ   34816                      // 128 rows x 272B
#define AKV    AQSZ
#define AKVSTR 34816                      // K(64x272) + V(64x272)
#define AVOF   17408
#define ATTN_SMEM (AQSZ + 2 * AKVSTR)     // 104448

__global__ __launch_bounds__(256) void attn_kernel(const int* __restrict__ flag)
{
    extern __shared__ __align__(16) char smraw[];
    const uint32_t sb = smem_u32(smraw);
    const int tid = threadIdx.x, w = tid >> 5, lane = tid & 31;
    const int qt = blockIdx.x, bh = blockIdx.y;
    const int b = bh >> 4, h = bh & 15;
    const int qbase = qt * 128;
    const int causal = *flag;

    const __half* Qh = g_qh + (size_t)bh * (TQ * HD);
    const __half* Kh = g_kh + (size_t)bh * (KVLEN * HD);
    const __half* Vh = g_vh + (size_t)bh * (KVLEN * HD);

    // Q tile -> smem (cp.async group 1)
#pragma unroll
    for (int i = 0; i < 8; i++) {
        int c = tid + i * 256;
        int row = c >> 4, kc = c & 15;
        cpa16(sb + row * 272 + kc * 16, Qh + (size_t)(qbase + row) * HD + kc * 8);
    }
    cpa_commit();
    // KV tile 0 (group 2)
    {
        const __half* srcs[2] = {Kh, Vh};
#pragma unroll
        for (int t = 0; t < 2; t++)
#pragma unroll
            for (int i = 0; i < 4; i++) {
                int c = tid + i * 256;
                int row = c >> 4, kc = c & 15;
                cpa16(sb + AKV + t * 17408 + row * 272 + kc * 16,
                      srcs[t] + (size_t)row * HD + kc * 8);
            }
        cpa_commit();
    }
    cpa_wait1();                 // Q done
    __syncthreads();

    // Q fragments (register-resident for the whole loop)
    uint32_t qf[8][4];
    {
        const uint32_t qrow = (uint32_t)(w * 16 + (lane & 15)) * 272;
#pragma unroll
        for (int ks = 0; ks < 8; ks++)
            ldm4(qf[ks], sb + qrow + ks * 32 + (lane >> 4) * 16);
    }

    float oacc[16][4];
#pragma unroll
    for (int nq = 0; nq < 16; nq++)
#pragma unroll
        for (int e = 0; e < 4; e++) oacc[nq][e] = 0.f;
    float mrow[2] = {-1e30f, -1e30f}, lrow[2] = {0.f, 0.f};

    const float scale2 = 0.12751879523525493f;   // log2(e)/sqrt(128)
    const int roff = KVLEN - TQ;
    int ntile = causal ? (2 * qt + 18) : 32;
    if (ntile > 32) ntile = 32;

    for (int kt = 0; kt < ntile; kt++) {
        cpa_wait0();
        __syncthreads();                          // KV tile kt ready, prev reads done
        const uint32_t kvst = sb + AKV + (kt & 1) * AKVSTR;

        if (kt + 1 < ntile) {                     // prefetch kt+1
            const uint32_t st = sb + AKV + ((kt + 1) & 1) * AKVSTR;
            const __half* srcs[2] = {Kh, Vh};
            const int nb2 = (kt + 1) * 64;
#pragma unroll
            for (int t = 0; t < 2; t++)
#pragma unroll
                for (int i = 0; i < 4; i++) {
                    int c = tid + i * 256;
                    int row = c >> 4, kc = c & 15;
                    cpa16(st + t * 17408 + row * 272 + kc * 16,
                          srcs[t] + (size_t)(nb2 + row) * HD + kc * 8);
                }
            cpa_commit();
        }

        // ---- S = Q K^T ----
        float sacc[8][4];
#pragma unroll
        for (int nt = 0; nt < 8; nt++)
#pragma unroll
            for (int e = 0; e < 4; e++) sacc[nt][e] = 0.f;

        const uint32_t krow = (uint32_t)(lane & 15) * 272;
#pragma unroll
        for (int ks = 0; ks < 8; ks++) {
            const uint32_t koff = ks * 32 + (lane >> 4) * 16;
            uint32_t kf[4][4];
#pragma unroll
            for (int np = 0; np < 4; np++)
                ldm4(kf[np], kvst + krow + np * 16 * 272 + koff);
#pragma unroll
            for (int nt = 0; nt < 8; nt++)
                mma16816(sacc[nt], qf[ks], kf[nt >> 1][nt & 1], kf[nt >> 1][(nt & 1) + 2]);
        }

        // ---- scale (log2-domain) + causal mask ----
        const int kbase = kt * 64;
        const int rglo = qbase + w * 16 + (lane >> 2) + roff;
#pragma unroll
        for (int nt = 0; nt < 8; nt++)
#pragma unroll
            for (int e = 0; e < 4; e++) {
                float v = sacc[nt][e] * scale2;
                if (causal) {
                    int cl = kbase + nt * 8 + (lane & 3) * 2 + (e & 1);
                    if (cl > rglo + (e >> 1) * 8) v = -1e30f;
                }
                sacc[nt][e] = v;
            }

        // ---- register softmax (quad shfl) ----
        float ml[2] = {-1e30f, -1e30f};
#pragma unroll
        for (int nt = 0; nt < 8; nt++) {
            ml[0] = fmaxf(ml[0], fmaxf(sacc[nt][0], sacc[nt][1]));
            ml[1] = fmaxf(ml[1], fmaxf(sacc[nt][2], sacc[nt][3]));
        }
#pragma unroll
        for (int i = 0; i < 2; i++) {
            ml[i] = fmaxf(ml[i], __shfl_xor_sync(0xffffffffu, ml[i], 1));
            ml[i] = fmaxf(ml[i], __shfl_xor_sync(0xffffffffu, ml[i], 2));
        }
        float mn[2], al[2];
#pragma unroll
        for (int i = 0; i < 2; i++) {
            mn[i] = fmaxf(mrow[i], ml[i]);
            al[i] = exp2f(mrow[i] - mn[i]);
            mrow[i] = mn[i];
        }
        float ls[2] = {0.f, 0.f};
#pragma unroll
        for (int nt = 0; nt < 8; nt++) {
            float p0 = exp2f(sacc[nt][0] - mn[0]);
            float p1 = exp2f(sacc[nt][1] - mn[0]);
            float p2 = exp2f(sacc[nt][2] - mn[1]);
            float p3 = exp2f(sacc[nt][3] - mn[1]);
            sacc[nt][0] = p0; sacc[nt][1] = p1; sacc[nt][2] = p2; sacc[nt][3] = p3;
            ls[0] += p0 + p1; ls[1] += p2 + p3;
        }
#pragma unroll
        for (int i = 0; i < 2; i++) {
            ls[i] += __shfl_xor_sync(0xffffffffu, ls[i], 1);
            ls[i] += __shfl_xor_sync(0xffffffffu, ls[i], 2);
            lrow[i] = lrow[i] * al[i] + ls[i];
        }
#pragma unroll
        for (int nq = 0; nq < 16; nq++) {
            oacc[nq][0] *= al[0]; oacc[nq][1] *= al[0];
            oacc[nq][2] *= al[1]; oacc[nq][3] *= al[1];
        }

        // ---- P fragments directly from S accumulators ----
        uint32_t pf[4][4];
#pragma unroll
        for (int kp = 0; kp < 4; kp++) {
            pf[kp][0] = packh2(sacc[2 * kp][0],     sacc[2 * kp][1]);
            pf[kp][1] = packh2(sacc[2 * kp][2],     sacc[2 * kp][3]);
            pf[kp][2] = packh2(sacc[2 * kp + 1][0], sacc[2 * kp + 1][1]);
            pf[kp][3] = packh2(sacc[2 * kp + 1][2], sacc[2 * kp + 1][3]);
        }

        // ---- O += P V ----
#pragma unroll
        for (int kp = 0; kp < 4; kp++) {
            const uint32_t vrow = (uint32_t)(kp * 16 + (lane & 15)) * 272 + (lane >> 4) * 16;
#pragma unroll
            for (int np = 0; np < 8; np++) {
                uint32_t vb[4];
                ldm4t(vb, kvst + AVOF + vrow + np * 32);
                mma16816(oacc[2 * np],     pf[kp], vb[0], vb[1]);
                mma16816(oacc[2 * np + 1], pf[kp], vb[2], vb[3]);
            }
        }
    }

    // ---- epilogue: O / l -> fp16 y (feeds proj directly) ----
#pragma unroll
    for (int i = 0; i < 2; i++) {
        float inv = 1.0f / lrow[i];
        int rl = w * 16 + (lane >> 2) + i * 8;
        __half* Yp = g_yh + (size_t)(b * TQ + qbase + rl) * D_MODEL + h * HD;
#pragma unroll
        for (int nq = 0; nq < 16; nq++) {
            int col = nq * 8 + (lane & 3) * 2;
            *(__half2*)(Yp + col) =
                __floats2half2_rn(oacc[nq][2 * i] * inv, oacc[nq][2 * i + 1] * inv);
        }
    }
}

// =====================================================================
// launch
// =====================================================================
extern "C" void kernel_launch(void* const* d_in, const int* in_sizes, int n_in,
                              void* d_out, int out_size)
{
    const float* x     = (const float*)d_in[0];
    const float* cosb  = (const float*)d_in[1];
    const float* sinb  = (const float*)d_in[2];
    const float* kxl   = (const float*)d_in[3];
    const float* vxl   = (const float*)d_in[4];
    const float* pos   = (const float*)d_in[5];
    const float* wqkv  = (const float*)d_in[6];
    const float* wproj = (const float*)d_in[7];
    const int*   flag  = (const int*)d_in[8];
    float*       out   = (float*)d_out;

    float* qkv;
    __half *ah, *bh, *yh;
    cudaGetSymbolAddress((void**)&qkv, g_qkv);
    cudaGetSymbolAddress((void**)&ah,  g_ah);
    cudaGetSymbolAddress((void**)&bh,  g_bh);
    cudaGetSymbolAddress((void**)&yh,  g_yh);

    cudaFuncSetAttribute(attn_kernel, cudaFuncAttributeMaxDynamicSharedMemorySize, ATTN_SMEM);
    cudaFuncSetAttribute(gemm_mma, cudaFuncAttributeMaxDynamicSharedMemorySize, GEMM_SMEM);

    const int nA  = MROWS * D_MODEL / 4;
    const int nBq = 3 * D_MODEL * D_MODEL / 4;
    const int nBp = D_MODEL * D_MODEL / 4;

    // 1) convert x, w_qkv; qkv = x @ w_qkv^T
    tohalf_kernel<<<(nA + 255) / 256, 256>>>(x, ah, nA);
    tohalf_kernel<<<(nBq + 255) / 256, 256>>>(wqkv, bh, nBq);
    gemm_mma<<<dim3(3 * D_MODEL / 128, MROWS / 256), 256, GEMM_SMEM>>>(
        ah, bh, qkv, MROWS, 3 * D_MODEL, D_MODEL);

    // 2) XL prep + RoPE scatter (fp16)
    xl_prep<<<(BATCH * XLLEN * D_MODEL / 2) / 256, 256>>>(kxl, vxl, pos);
    rope_split<<<(BATCH * TQ * NHEADS * 64) / 256, 256>>>(cosb, sinb);

    // 3) flash attention -> fp16 y
    attn_kernel<<<dim3(TQ / 128, BATCH * NHEADS), 256, ATTN_SMEM>>>(flag);

    // 4) convert w_proj; out = y @ w_proj^T
    tohalf_kernel<<<(nBp + 255) / 256, 256>>>(wproj, bh, nBp);
    gemm_mma<<<dim3(D_MODEL / 128, MROWS / 256), 256, GEMM_SMEM>>>(
        yh, bh, out, MROWS, D_MODEL, D_MODEL);
}

// round 7
// speedup vs baseline: 5.7658x; 1.0519x over previous
#include <cuda_runtime.h>
#include <cuda_fp16.h>
#include <cstdint>

#define D_MODEL 2048
#define NHEADS  16
#define HD      128
#define BATCH   2
#define TQ      1024
#define XLLEN   1024
#define KVLEN   2048
#define MROWS   (BATCH * TQ)    // 2048

// ---------------- scratch (device globals) ----------------
__device__ __half g_yh [(size_t)MROWS * D_MODEL];
__device__ __half g_qh [(size_t)BATCH * NHEADS * TQ * HD];
__device__ __half g_kh [(size_t)BATCH * NHEADS * KVLEN * HD];
__device__ __half g_vh [(size_t)BATCH * NHEADS * KVLEN * HD];
__device__ __half g_ah [(size_t)MROWS * D_MODEL];
__device__ __half g_bh [(size_t)3 * D_MODEL * D_MODEL];
__device__ __half g_bp [(size_t)D_MODEL * D_MODEL];

// ======================= PTX helpers =======================
__device__ __forceinline__ uint32_t smem_u32(const void* p) {
    uint32_t a;
    asm("{ .reg .u64 t; cvta.to.shared.u64 t, %1; cvt.u32.u64 %0, t; }" : "=r"(a) : "l"(p));
    return a;
}
__device__ __forceinline__ void ldm4(uint32_t* r, uint32_t a) {
    asm volatile("ldmatrix.sync.aligned.m8n8.x4.shared.b16 {%0,%1,%2,%3}, [%4];"
                 : "=r"(r[0]), "=r"(r[1]), "=r"(r[2]), "=r"(r[3]) : "r"(a));
}
__device__ __forceinline__ void ldm4t(uint32_t* r, uint32_t a) {
    asm volatile("ldmatrix.sync.aligned.m8n8.x4.trans.shared.b16 {%0,%1,%2,%3}, [%4];"
                 : "=r"(r[0]), "=r"(r[1]), "=r"(r[2]), "=r"(r[3]) : "r"(a));
}
__device__ __forceinline__ void mma16816(float* d, const uint32_t* a, uint32_t b0, uint32_t b1) {
    asm volatile("mma.sync.aligned.m16n8k16.row.col.f32.f16.f16.f32 "
                 "{%0,%1,%2,%3}, {%4,%5,%6,%7}, {%8,%9}, {%0,%1,%2,%3};"
                 : "+f"(d[0]), "+f"(d[1]), "+f"(d[2]), "+f"(d[3])
                 : "r"(a[0]), "r"(a[1]), "r"(a[2]), "r"(a[3]), "r"(b0), "r"(b1));
}
__device__ __forceinline__ void cpa16(uint32_t dst, const void* src) {
    asm volatile("cp.async.cg.shared.global [%0], [%1], 16;" :: "r"(dst), "l"(src));
}
__device__ __forceinline__ void cpa_commit() { asm volatile("cp.async.commit_group;" ::: "memory"); }
__device__ __forceinline__ void cpa_wait1()  { asm volatile("cp.async.wait_group 1;" ::: "memory"); }
__device__ __forceinline__ void cpa_wait0()  { asm volatile("cp.async.wait_group 0;" ::: "memory"); }
// packed-half exp2: converts (a,b) to half2, one MUFU op for both lanes
__device__ __forceinline__ uint32_t ex2h2(float a, float b) {
    __half2 t = __floats2half2_rn(a, b);
    uint32_t u = *(uint32_t*)&t, r;
    asm("ex2.approx.f16x2 %0, %1;" : "=r"(r) : "r"(u));
    return r;
}

// =====================================================================
// prep: fp32->fp16 for x/wqkv/wproj + XL K/V prep, one segmented grid
// =====================================================================
__global__ void prep_kernel(const float* __restrict__ x, const float* __restrict__ wqkv,
                            const float* __restrict__ wproj, const float* __restrict__ kxl,
                            const float* __restrict__ vxl, const float* __restrict__ pos)
{
    const int blk = blockIdx.x;
    if (blk < 20480) {
        const float* src; __half* dst; int i;
        if (blk < 4096)       { src = x;     dst = g_ah; i = blk * 256 + threadIdx.x; }
        else if (blk < 16384) { src = wqkv;  dst = g_bh; i = (blk - 4096) * 256 + threadIdx.x; }
        else                  { src = wproj; dst = g_bp; i = (blk - 16384) * 256 + threadIdx.x; }
        float4 v = ((const float4*)src)[i];
        __half h[4] = {__float2half_rn(v.x), __float2half_rn(v.y),
                       __float2half_rn(v.z), __float2half_rn(v.w)};
        *(uint2*)(dst + (size_t)i * 4) = *(uint2*)h;
    } else {
        int idx = (blk - 20480) * 256 + threadIdx.x;    // B*XL*D/2
        int c2 = idx & 1023;
        int t  = (idx >> 10) & 1023;
        int b  = idx >> 20;
        int c = c2 * 2;
        int h = c >> 7, d = c & 127;
        size_t src = ((size_t)(b * XLLEN + t)) * D_MODEL + c;
        float2 kv = *(const float2*)(kxl + src);
        float2 pv = *(const float2*)(pos + (size_t)t * D_MODEL + c);
        float2 vv = *(const float2*)(vxl + src);
        size_t dst = ((size_t)((b * NHEADS + h) * KVLEN + t)) * HD + d;
        *(__half2*)&g_kh[dst] = __floats2half2_rn(kv.x + pv.x, kv.y + pv.y);
        *(__half2*)&g_vh[dst] = __floats2half2_rn(vv.x, vv.y);
    }
}

// =====================================================================
// fp16 mma.sync NT GEMM: 256x128 CTA tile, BK=32, 8 warps (64x64),
// 3-stage cp.async.  MODE 0: plain fp32 C store.
// MODE 1: fused RoPE + q/k/v scatter epilogue (writes fp16 scratch).
// =====================================================================
#define GA_B   20480              // 256 rows x 80B
#define GB_B   10240              // 128 rows x 80B
#define GSTG_B (GA_B + GB_B)      // 30720
#define GEMM_SMEM (3 * GSTG_B)    // 92160

template<int MODE>
__global__ __launch_bounds__(256) void gemm_mma(
    const __half* __restrict__ A, const __half* __restrict__ B,
    float* __restrict__ C, const float* __restrict__ cosb, const float* __restrict__ sinb,
    int M, int N, int K)
{
    extern __shared__ __align__(16) char smraw[];
    const uint32_t sb = smem_u32(smraw);
    const int tid = threadIdx.x, wid = tid >> 5, lane = tid & 31;
    const int wm = wid & 3, wn = wid >> 2;
    const int mb = blockIdx.y * 256, nb = blockIdx.x * 128;

    const __half* Asrc = A + (size_t)mb * K;
    const __half* Bsrc = B + (size_t)nb * K;
    const int NKB = K >> 5;

    // prologue: stages 0, 1
#pragma unroll
    for (int s = 0; s < 2; s++) {
        const uint32_t st = sb + s * GSTG_B;
        const int ko = s * 32;
#pragma unroll
        for (int i = 0; i < 4; i++) {
            int c = tid + i * 256;
            int row = c >> 2, kc = c & 3;
            cpa16(st + row * 80 + kc * 16, Asrc + (size_t)row * K + ko + kc * 8);
        }
#pragma unroll
        for (int i = 0; i < 2; i++) {
            int c = tid + i * 256;
            int row = c >> 2, kc = c & 3;
            cpa16(st + GA_B + row * 80 + kc * 16, Bsrc + (size_t)row * K + ko + kc * 8);
        }
        cpa_commit();
    }

    float acc[4][8][4];
#pragma unroll
    for (int a = 0; a < 4; a++)
#pragma unroll
        for (int b = 0; b < 8; b++)
#pragma unroll
            for (int e = 0; e < 4; e++) acc[a][b][e] = 0.f;

    for (int kb = 0; kb < NKB; kb++) {
        if (kb + 1 < NKB) cpa_wait1(); else cpa_wait0();
        __syncthreads();

        if (kb + 2 < NKB) {
            const uint32_t st = sb + ((kb + 2) % 3) * GSTG_B;
            const int ko = (kb + 2) * 32;
#pragma unroll
            for (int i = 0; i < 4; i++) {
                int c = tid + i * 256;
                int row = c >> 2, kc = c & 3;
                cpa16(st + row * 80 + kc * 16, Asrc + (size_t)row * K + ko + kc * 8);
            }
#pragma unroll
            for (int i = 0; i < 2; i++) {
                int c = tid + i * 256;
                int row = c >> 2, kc = c & 3;
                cpa16(st + GA_B + row * 80 + kc * 16, Bsrc + (size_t)row * K + ko + kc * 8);
            }
            cpa_commit();
        }

        const uint32_t st = sb + (kb % 3) * GSTG_B;
        const uint32_t arow = (uint32_t)(wm * 64 + (lane & 15)) * 80;
        const uint32_t brow = (uint32_t)(wn * 64 + (lane & 15)) * 80;
#pragma unroll
        for (int ks = 0; ks < 2; ks++) {
            const uint32_t koff = ks * 32 + (lane >> 4) * 16;
            uint32_t Af[4][4], Bf[4][4];
#pragma unroll
            for (int mt = 0; mt < 4; mt++)
                ldm4(Af[mt], st + arow + mt * 16 * 80 + koff);
#pragma unroll
            for (int np = 0; np < 4; np++)
                ldm4(Bf[np], st + GA_B + brow + np * 16 * 80 + koff);
#pragma unroll
            for (int mt = 0; mt < 4; mt++)
#pragma unroll
                for (int nt = 0; nt < 8; nt++)
                    mma16816(acc[mt][nt], Af[mt], Bf[nt >> 1][nt & 1], Bf[nt >> 1][(nt & 1) + 2]);
        }
    }

    if (MODE == 0) {
        // plain fp32 store
#pragma unroll
        for (int mt = 0; mt < 4; mt++) {
            int row0 = mb + wm * 64 + mt * 16 + (lane >> 2);
#pragma unroll
            for (int nt = 0; nt < 8; nt++) {
                int col = nb + wn * 64 + nt * 8 + (lane & 3) * 2;
                *(float2*)&C[(size_t)row0 * N + col]       = make_float2(acc[mt][nt][0], acc[mt][nt][1]);
                *(float2*)&C[(size_t)(row0 + 8) * N + col] = make_float2(acc[mt][nt][2], acc[mt][nt][3]);
            }
        }
    } else {
        // fused RoPE + scatter. Per CTA: region (q/k/v) and head are uniform;
        // within-tile col == head-dim index d; fragment pairs are (even,odd) d.
        const int region = nb >> 11;
        const int hh = (nb & 2047) >> 7;
#pragma unroll
        for (int mt = 0; mt < 4; mt++) {
#pragma unroll
            for (int i = 0; i < 2; i++) {
                int row = mb + wm * 64 + mt * 16 + (lane >> 2) + i * 8;
                int bb = row >> 10, t = row & 1023;
#pragma unroll
                for (int nt = 0; nt < 8; nt++) {
                    int d = wn * 64 + nt * 8 + (lane & 3) * 2;
                    float a0 = acc[mt][nt][2 * i], a1 = acc[mt][nt][2 * i + 1];
                    if (region == 2) {
                        size_t dst = ((size_t)(bb * NHEADS + hh) * KVLEN + XLLEN + t) * HD + d;
                        *(__half2*)&g_vh[dst] = __floats2half2_rn(a0, a1);
                    } else {
                        int dp = d >> 1;
                        float cv = cosb[t * 64 + dp], sv = sinb[t * 64 + dp];
                        float o0 = a0 * cv - a1 * sv;
                        float o1 = a0 * sv + a1 * cv;
                        if (region == 0) {
                            size_t dst = ((size_t)(bb * NHEADS + hh) * TQ + t) * HD + d;
                            *(__half2*)&g_qh[dst] = __floats2half2_rn(o0, o1);
                        } else {
                            size_t dst = ((size_t)(bb * NHEADS + hh) * KVLEN + XLLEN + t) * HD + d;
                            *(__half2*)&g_kh[dst] = __floats2half2_rn(o0, o1);
                        }
                    }
                }
            }
        }
    }
}

// =====================================================================
// Flash attention FA2: BQ=128, BK=64, D=128, 8 warps.
// 3-buffer KV cp.async pipeline (prefetch issued before wait);
// softmax exp via ex2.approx.f16x2 -> results ARE the P fragments.
// =====================================================================
#define AQSZ   34816                      // 128 rows x 272B
#define AKV    AQSZ
#define AKVSTG 34816                      // K(64x272) + V(64x272)
#define AVOF   17408
#define ATTN_SMEM (AQSZ + 3 * AKVSTG)     // 139264

__global__ __launch_bounds__(256) void attn_kernel(const int* __restrict__ flag)
{
    extern __shared__ __align__(16) char smraw[];
    const uint32_t sb = smem_u32(smraw);
    const int tid = threadIdx.x, w = tid >> 5, lane = tid & 31;
    const int qt = blockIdx.x, bh = blockIdx.y;
    const int b = bh >> 4, h = bh & 15;
    const int qbase = qt * 128;
    const int causal = *flag;

    const __half* Qh = g_qh + (size_t)bh * (TQ * HD);
    const __half* Kh = g_kh + (size_t)bh * (KVLEN * HD);
    const __half* Vh = g_vh + (size_t)bh * (KVLEN * HD);

    // Q tile (group 0)
#pragma unroll
    for (int i = 0; i < 8; i++) {
        int c = tid + i * 256;
        int row = c >> 4, kc = c & 15;
        cpa16(sb + row * 272 + kc * 16, Qh + (size_t)(qbase + row) * HD + kc * 8);
    }
    cpa_commit();
    // KV tile 0 (group 1)
    {
        const __half* srcs[2] = {Kh, Vh};
#pragma unroll
        for (int t = 0; t < 2; t++)
#pragma unroll
            for (int i = 0; i < 4; i++) {
                int c = tid + i * 256;
                int row = c >> 4, kc = c & 15;
                cpa16(sb + AKV + t * 17408 + row * 272 + kc * 16,
                      srcs[t] + (size_t)row * HD + kc * 8);
            }
        cpa_commit();
    }
    cpa_wait1();                 // Q arrived
    __syncthreads();

    // Q fragments register-resident
    uint32_t qf[8][4];
    {
        const uint32_t qrow = (uint32_t)(w * 16 + (lane & 15)) * 272;
#pragma unroll
        for (int ks = 0; ks < 8; ks++)
            ldm4(qf[ks], sb + qrow + ks * 32 + (lane >> 4) * 16);
    }

    float oacc[16][4];
#pragma unroll
    for (int nq = 0; nq < 16; nq++)
#pragma unroll
        for (int e = 0; e < 4; e++) oacc[nq][e] = 0.f;
    float mrow[2] = {-1e30f, -1e30f}, lrow[2] = {0.f, 0.f};

    const float scale2 = 0.12751879523525493f;   // log2(e)/sqrt(128)
    const int roff = KVLEN - TQ;
    int ntile = causal ? (2 * qt + 18) : 32;
    if (ntile > 32) ntile = 32;

    for (int kt = 0; kt < ntile; kt++) {
        if (kt + 1 < ntile) {                       // prefetch into buf (kt+1)%3
            const uint32_t st = sb + AKV + ((kt + 1) % 3) * AKVSTG;
            const __half* srcs[2] = {Kh, Vh};
            const int nb2 = (kt + 1) * 64;
#pragma unroll
            for (int t = 0; t < 2; t++)
#pragma unroll
                for (int i = 0; i < 4; i++) {
                    int c = tid + i * 256;
                    int row = c >> 4, kc = c & 15;
                    cpa16(st + t * 17408 + row * 272 + kc * 16,
                          srcs[t] + (size_t)(nb2 + row) * HD + kc * 8);
                }
            cpa_commit();
            cpa_wait1();                            // tile kt arrived
        } else {
            cpa_wait0();
        }
        __syncthreads();
        const uint32_t kvst = sb + AKV + (kt % 3) * AKVSTG;

        // ---- S = Q K^T ----
        float sacc[8][4];
#pragma unroll
        for (int nt = 0; nt < 8; nt++)
#pragma unroll
            for (int e = 0; e < 4; e++) sacc[nt][e] = 0.f;

        const uint32_t krow = (uint32_t)(lane & 15) * 272;
#pragma unroll
        for (int ks = 0; ks < 8; ks++) {
            const uint32_t koff = ks * 32 + (lane >> 4) * 16;
            uint32_t kf[4][4];
#pragma unroll
            for (int np = 0; np < 4; np++)
                ldm4(kf[np], kvst + krow + np * 16 * 272 + koff);
#pragma unroll
            for (int nt = 0; nt < 8; nt++)
                mma16816(sacc[nt], qf[ks], kf[nt >> 1][nt & 1], kf[nt >> 1][(nt & 1) + 2]);
        }

        // ---- scale to log2 domain; mask only if causal (uniform branch) ----
#pragma unroll
        for (int nt = 0; nt < 8; nt++)
#pragma unroll
            for (int e = 0; e < 4; e++) sacc[nt][e] *= scale2;
        if (causal) {
            const int kbase = kt * 64;
            const int rglo = qbase + w * 16 + (lane >> 2) + roff;
#pragma unroll
            for (int nt = 0; nt < 8; nt++)
#pragma unroll
                for (int e = 0; e < 4; e++) {
                    int cl = kbase + nt * 8 + (lane & 3) * 2 + (e & 1);
                    if (cl > rglo + (e >> 1) * 8) sacc[nt][e] = -1e30f;
                }
        }

        // ---- register softmax (quad shfl) ----
        float ml[2] = {-1e30f, -1e30f};
#pragma unroll
        for (int nt = 0; nt < 8; nt++) {
            ml[0] = fmaxf(ml[0], fmaxf(sacc[nt][0], sacc[nt][1]));
            ml[1] = fmaxf(ml[1], fmaxf(sacc[nt][2], sacc[nt][3]));
        }
#pragma unroll
        for (int i = 0; i < 2; i++) {
            ml[i] = fmaxf(ml[i], __shfl_xor_sync(0xffffffffu, ml[i], 1));
            ml[i] = fmaxf(ml[i], __shfl_xor_sync(0xffffffffu, ml[i], 2));
        }
        float mn[2], al[2];
#pragma unroll
        for (int i = 0; i < 2; i++) {
            mn[i] = fmaxf(mrow[i], ml[i]);
            al[i] = exp2f(mrow[i] - mn[i]);
            mrow[i] = mn[i];
        }

        // ---- P = exp2(S - m) in packed fp16: one MUFU per 2 values,
        //      results are directly the PV A-fragments ----
        float ls[2] = {0.f, 0.f};
        uint32_t pf[4][4];
#pragma unroll
        for (int nt = 0; nt < 8; nt++) {
            uint32_t p01 = ex2h2(sacc[nt][0] - mn[0], sacc[nt][1] - mn[0]);
            uint32_t p23 = ex2h2(sacc[nt][2] - mn[1], sacc[nt][3] - mn[1]);
            pf[nt >> 1][(nt & 1) * 2 + 0] = p01;
            pf[nt >> 1][(nt & 1) * 2 + 1] = p23;
            float2 f0 = __half22float2(*(__half2*)&p01);
            float2 f1 = __half22float2(*(__half2*)&p23);
            ls[0] += f0.x + f0.y;
            ls[1] += f1.x + f1.y;
        }
#pragma unroll
        for (int i = 0; i < 2; i++) {
            ls[i] += __shfl_xor_sync(0xffffffffu, ls[i], 1);
            ls[i] += __shfl_xor_sync(0xffffffffu, ls[i], 2);
            lrow[i] = lrow[i] * al[i] + ls[i];
        }
#pragma unroll
        for (int nq = 0; nq < 16; nq++) {
            oacc[nq][0] *= al[0]; oacc[nq][1] *= al[0];
            oacc[nq][2] *= al[1]; oacc[nq][3] *= al[1];
        }

        // ---- O += P V ----
#pragma unroll
        for (int kp = 0; kp < 4; kp++) {
            const uint32_t vrow = (uint32_t)(kp * 16 + (lane & 15)) * 272 + (lane >> 4) * 16;
#pragma unroll
            for (int np = 0; np < 8; np++) {
                uint32_t vb[4];
                ldm4t(vb, kvst + AVOF + vrow + np * 32);
                mma16816(oacc[2 * np],     pf[kp], vb[0], vb[1]);
                mma16816(oacc[2 * np + 1], pf[kp], vb[2], vb[3]);
            }
        }
    }

    // ---- epilogue: O / l -> fp16 y ----
#pragma unroll
    for (int i = 0; i < 2; i++) {
        float inv = 1.0f / lrow[i];
        int rl = w * 16 + (lane >> 2) + i * 8;
        __half* Yp = g_yh + (size_t)(b * TQ + qbase + rl) * D_MODEL + h * HD;
#pragma unroll
        for (int nq = 0; nq < 16; nq++) {
            int col = nq * 8 + (lane & 3) * 2;
            *(__half2*)(Yp + col) =
                __floats2half2_rn(oacc[nq][2 * i] * inv, oacc[nq][2 * i + 1] * inv);
        }
    }
}

// =====================================================================
// launch
// =====================================================================
extern "C" void kernel_launch(void* const* d_in, const int* in_sizes, int n_in,
                              void* d_out, int out_size)
{
    const float* x     = (const float*)d_in[0];
    const float* cosb  = (const float*)d_in[1];
    const float* sinb  = (const float*)d_in[2];
    const float* kxl   = (const float*)d_in[3];
    const float* vxl   = (const float*)d_in[4];
    const float* pos   = (const float*)d_in[5];
    const float* wqkv  = (const float*)d_in[6];
    const float* wproj = (const float*)d_in[7];
    const int*   flag  = (const int*)d_in[8];
    float*       out   = (float*)d_out;

    __half *ah, *bh, *bp, *yh;
    cudaGetSymbolAddress((void**)&ah, g_ah);
    cudaGetSymbolAddress((void**)&bh, g_bh);
    cudaGetSymbolAddress((void**)&bp, g_bp);
    cudaGetSymbolAddress((void**)&yh, g_yh);

    cudaFuncSetAttribute(attn_kernel, cudaFuncAttributeMaxDynamicSharedMemorySize, ATTN_SMEM);
    cudaFuncSetAttribute(gemm_mma<0>, cudaFuncAttributeMaxDynamicSharedMemorySize, GEMM_SMEM);
    cudaFuncSetAttribute(gemm_mma<1>, cudaFuncAttributeMaxDynamicSharedMemorySize, GEMM_SMEM);

    // 1) all conversions + XL prep, one segmented launch
    prep_kernel<<<28672, 256>>>(x, wqkv, wproj, kxl, vxl, pos);

    // 2) qkv GEMM with fused RoPE + q/k/v scatter (fp16 out)
    gemm_mma<1><<<dim3(3 * D_MODEL / 128, MROWS / 256), 256, GEMM_SMEM>>>(
        ah, bh, nullptr, cosb, sinb, MROWS, 3 * D_MODEL, D_MODEL);

    // 3) flash attention -> fp16 y
    attn_kernel<<<dim3(TQ / 128, BATCH * NHEADS), 256, ATTN_SMEM>>>(flag);

    // 4) out = y @ w_proj^T
    gemm_mma<0><<<dim3(D_MODEL / 128, MROWS / 256), 256, GEMM_SMEM>>>(
        yh, bp, out, nullptr, nullptr, MROWS, D_MODEL, D_MODEL);
}

// round 8
// speedup vs baseline: 5.9889x; 1.0387x over previous
#include <cuda_runtime.h>
#include <cuda_fp16.h>
#include <cstdint>

#define D_MODEL 2048
#define NHEADS  16
#define HD      128
#define BATCH   2
#define TQ      1024
#define XLLEN   1024
#define KVLEN   2048
#define MROWS   (BATCH * TQ)    // 2048

// ---------------- scratch (device globals) ----------------
__device__ __half g_yh [(size_t)MROWS * D_MODEL];
__device__ __half g_qh [(size_t)BATCH * NHEADS * TQ * HD];
__device__ __half g_kh [(size_t)BATCH * NHEADS * KVLEN * HD];
__device__ __half g_vh [(size_t)BATCH * NHEADS * KVLEN * HD];
__device__ __half g_ah [(size_t)MROWS * D_MODEL];
__device__ __half g_bh [(size_t)3 * D_MODEL * D_MODEL];
__device__ __half g_bp [(size_t)D_MODEL * D_MODEL];

// ======================= PTX helpers =======================
__device__ __forceinline__ uint32_t smem_u32(const void* p) {
    uint32_t a;
    asm("{ .reg .u64 t; cvta.to.shared.u64 t, %1; cvt.u32.u64 %0, t; }" : "=r"(a) : "l"(p));
    return a;
}
__device__ __forceinline__ void ldm4(uint32_t* r, uint32_t a) {
    asm volatile("ldmatrix.sync.aligned.m8n8.x4.shared.b16 {%0,%1,%2,%3}, [%4];"
                 : "=r"(r[0]), "=r"(r[1]), "=r"(r[2]), "=r"(r[3]) : "r"(a));
}
__device__ __forceinline__ void ldm4t(uint32_t* r, uint32_t a) {
    asm volatile("ldmatrix.sync.aligned.m8n8.x4.trans.shared.b16 {%0,%1,%2,%3}, [%4];"
                 : "=r"(r[0]), "=r"(r[1]), "=r"(r[2]), "=r"(r[3]) : "r"(a));
}
__device__ __forceinline__ void mma16816(float* d, const uint32_t* a, uint32_t b0, uint32_t b1) {
    asm volatile("mma.sync.aligned.m16n8k16.row.col.f32.f16.f16.f32 "
                 "{%0,%1,%2,%3}, {%4,%5,%6,%7}, {%8,%9}, {%0,%1,%2,%3};"
                 : "+f"(d[0]), "+f"(d[1]), "+f"(d[2]), "+f"(d[3])
                 : "r"(a[0]), "r"(a[1]), "r"(a[2]), "r"(a[3]), "r"(b0), "r"(b1));
}
__device__ __forceinline__ void cpa16(uint32_t dst, const void* src) {
    asm volatile("cp.async.cg.shared.global [%0], [%1], 16;" :: "r"(dst), "l"(src));
}
__device__ __forceinline__ void cpa_commit() { asm volatile("cp.async.commit_group;" ::: "memory"); }
__device__ __forceinline__ void cpa_wait2()  { asm volatile("cp.async.wait_group 2;" ::: "memory"); }
__device__ __forceinline__ void cpa_wait1()  { asm volatile("cp.async.wait_group 1;" ::: "memory"); }
__device__ __forceinline__ void cpa_wait0()  { asm volatile("cp.async.wait_group 0;" ::: "memory"); }
// packed-half exp2: one MUFU op for two values; results are P fragments
__device__ __forceinline__ uint32_t ex2h2(float a, float b) {
    __half2 t = __floats2half2_rn(a, b);
    uint32_t u = *(uint32_t*)&t, r;
    asm("ex2.approx.f16x2 %0, %1;" : "=r"(r) : "r"(u));
    return r;
}

// =====================================================================
// prep: fp32->fp16 for x/wqkv/wproj + XL K/V prep, one segmented grid
// =====================================================================
__global__ void prep_kernel(const float* __restrict__ x, const float* __restrict__ wqkv,
                            const float* __restrict__ wproj, const float* __restrict__ kxl,
                            const float* __restrict__ vxl, const float* __restrict__ pos)
{
    const int blk = blockIdx.x;
    if (blk < 20480) {
        const float* src; __half* dst; int i;
        if (blk < 4096)       { src = x;     dst = g_ah; i = blk * 256 + threadIdx.x; }
        else if (blk < 16384) { src = wqkv;  dst = g_bh; i = (blk - 4096) * 256 + threadIdx.x; }
        else                  { src = wproj; dst = g_bp; i = (blk - 16384) * 256 + threadIdx.x; }
        float4 v = ((const float4*)src)[i];
        __half h[4] = {__float2half_rn(v.x), __float2half_rn(v.y),
                       __float2half_rn(v.z), __float2half_rn(v.w)};
        *(uint2*)(dst + (size_t)i * 4) = *(uint2*)h;
    } else {
        int idx = (blk - 20480) * 256 + threadIdx.x;    // B*XL*D/2
        int c2 = idx & 1023;
        int t  = (idx >> 10) & 1023;
        int b  = idx >> 20;
        int c = c2 * 2;
        int h = c >> 7, d = c & 127;
        size_t src = ((size_t)(b * XLLEN + t)) * D_MODEL + c;
        float2 kv = *(const float2*)(kxl + src);
        float2 pv = *(const float2*)(pos + (size_t)t * D_MODEL + c);
        float2 vv = *(const float2*)(vxl + src);
        size_t dst = ((size_t)((b * NHEADS + h) * KVLEN + t)) * HD + d;
        *(__half2*)&g_kh[dst] = __floats2half2_rn(kv.x + pv.x, kv.y + pv.y);
        *(__half2*)&g_vh[dst] = __floats2half2_rn(vv.x, vv.y);
    }
}

// =====================================================================
// fp16 mma.sync NT GEMM: 128x128 CTA tile, BK=32, 8 warps (64x32),
// 4-stage cp.async, 2 CTAs/SM (launch_bounds).  MODE 0: fp32 C.
// MODE 1: fused RoPE + q/k/v scatter epilogue.
// =====================================================================
#define GTILE_B  10240            // 128 rows x 80B
#define GSTG_B   (2 * GTILE_B)    // A + B
#define GEMM_SMEM (4 * GSTG_B)    // 81920

template<int MODE>
__global__ __launch_bounds__(256, 2) void gemm_mma(
    const __half* __restrict__ A, const __half* __restrict__ B,
    float* __restrict__ C, const float* __restrict__ cosb, const float* __restrict__ sinb,
    int M, int N, int K)
{
    extern __shared__ __align__(16) char smraw[];
    const uint32_t sb = smem_u32(smraw);
    const int tid = threadIdx.x, wid = tid >> 5, lane = tid & 31;
    const int wm = wid & 1, wn = wid >> 1;
    const int mb = blockIdx.y * 128, nb = blockIdx.x * 128;

    const __half* Asrc = A + (size_t)mb * K;
    const __half* Bsrc = B + (size_t)nb * K;
    const int NKB = K >> 5;

    // prologue: stages 0..2
#pragma unroll
    for (int s = 0; s < 3; s++) {
        const uint32_t st = sb + s * GSTG_B;
        const int ko = s * 32;
#pragma unroll
        for (int i = 0; i < 2; i++) {
            int c = tid + i * 256;
            int row = c >> 2, kc = c & 3;
            cpa16(st + row * 80 + kc * 16, Asrc + (size_t)row * K + ko + kc * 8);
            cpa16(st + GTILE_B + row * 80 + kc * 16, Bsrc + (size_t)row * K + ko + kc * 8);
        }
        cpa_commit();
    }

    float acc[4][4][4];
#pragma unroll
    for (int a = 0; a < 4; a++)
#pragma unroll
        for (int b = 0; b < 4; b++)
#pragma unroll
            for (int e = 0; e < 4; e++) acc[a][b][e] = 0.f;

    for (int kb = 0; kb < NKB; kb++) {
        if (kb + 3 < NKB) cpa_wait2();
        else if (kb + 2 < NKB) cpa_wait1();
        else cpa_wait0();
        __syncthreads();

        if (kb + 3 < NKB) {
            const uint32_t st = sb + ((kb + 3) & 3) * GSTG_B;
            const int ko = (kb + 3) * 32;
#pragma unroll
            for (int i = 0; i < 2; i++) {
                int c = tid + i * 256;
                int row = c >> 2, kc = c & 3;
                cpa16(st + row * 80 + kc * 16, Asrc + (size_t)row * K + ko + kc * 8);
                cpa16(st + GTILE_B + row * 80 + kc * 16, Bsrc + (size_t)row * K + ko + kc * 8);
            }
            cpa_commit();
        }

        const uint32_t st = sb + (kb & 3) * GSTG_B;
        const uint32_t arow = (uint32_t)(wm * 64 + (lane & 15)) * 80;
        const uint32_t brow = (uint32_t)(wn * 32 + (lane & 15)) * 80;
#pragma unroll
        for (int ks = 0; ks < 2; ks++) {
            const uint32_t koff = ks * 32 + (lane >> 4) * 16;
            uint32_t Af[4][4], Bf[2][4];
#pragma unroll
            for (int mt = 0; mt < 4; mt++)
                ldm4(Af[mt], st + arow + mt * 16 * 80 + koff);
#pragma unroll
            for (int np = 0; np < 2; np++)
                ldm4(Bf[np], st + GTILE_B + brow + np * 16 * 80 + koff);
#pragma unroll
            for (int mt = 0; mt < 4; mt++)
#pragma unroll
                for (int nt = 0; nt < 4; nt++)
                    mma16816(acc[mt][nt], Af[mt], Bf[nt >> 1][nt & 1], Bf[nt >> 1][(nt & 1) + 2]);
        }
        __syncthreads();
    }

    if (MODE == 0) {
#pragma unroll
        for (int mt = 0; mt < 4; mt++) {
            int row0 = mb + wm * 64 + mt * 16 + (lane >> 2);
#pragma unroll
            for (int nt = 0; nt < 4; nt++) {
                int col = nb + wn * 32 + nt * 8 + (lane & 3) * 2;
                *(float2*)&C[(size_t)row0 * N + col]       = make_float2(acc[mt][nt][0], acc[mt][nt][1]);
                *(float2*)&C[(size_t)(row0 + 8) * N + col] = make_float2(acc[mt][nt][2], acc[mt][nt][3]);
            }
        }
    } else {
        // fused RoPE + scatter; region (q/k/v) and head are CTA-uniform.
        const int region = nb >> 11;
        const int hh = (nb & 2047) >> 7;
#pragma unroll
        for (int mt = 0; mt < 4; mt++) {
#pragma unroll
            for (int i = 0; i < 2; i++) {
                int row = mb + wm * 64 + mt * 16 + (lane >> 2) + i * 8;
                int bb = row >> 10, t = row & 1023;
#pragma unroll
                for (int nt = 0; nt < 4; nt++) {
                    int d = wn * 32 + nt * 8 + (lane & 3) * 2;
                    float a0 = acc[mt][nt][2 * i], a1 = acc[mt][nt][2 * i + 1];
                    if (region == 2) {
                        size_t dst = ((size_t)(bb * NHEADS + hh) * KVLEN + XLLEN + t) * HD + d;
                        *(__half2*)&g_vh[dst] = __floats2half2_rn(a0, a1);
                    } else {
                        int dp = d >> 1;
                        float cv = cosb[t * 64 + dp], sv = sinb[t * 64 + dp];
                        float o0 = a0 * cv - a1 * sv;
                        float o1 = a0 * sv + a1 * cv;
                        if (region == 0) {
                            size_t dst = ((size_t)(bb * NHEADS + hh) * TQ + t) * HD + d;
                            *(__half2*)&g_qh[dst] = __floats2half2_rn(o0, o1);
                        } else {
                            size_t dst = ((size_t)(bb * NHEADS + hh) * KVLEN + XLLEN + t) * HD + d;
                            *(__half2*)&g_kh[dst] = __floats2half2_rn(o0, o1);
                        }
                    }
                }
            }
        }
    }
}

// =====================================================================
// Flash attention FA2: BQ=128, BK=128, D=128, 8 warps, 2-stage KV.
// softmax exp via ex2.approx.f16x2; P fragments straight from S regs.
// =====================================================================
#define AQSZ   34816                      // 128 rows x 272B
#define AKV    AQSZ
#define AKVSTG 69632                      // K(128x272) + V(128x272)
#define AVOF   34816
#define ATTN_SMEM (AQSZ + 2 * AKVSTG)     // 174080

__global__ __launch_bounds__(256) void attn_kernel(const int* __restrict__ flag)
{
    extern __shared__ __align__(16) char smraw[];
    const uint32_t sb = smem_u32(smraw);
    const int tid = threadIdx.x, w = tid >> 5, lane = tid & 31;
    const int qt = blockIdx.x, bh = blockIdx.y;
    const int b = bh >> 4, h = bh & 15;
    const int qbase = qt * 128;
    const int causal = *flag;

    const __half* Qh = g_qh + (size_t)bh * (TQ * HD);
    const __half* Kh = g_kh + (size_t)bh * (KVLEN * HD);
    const __half* Vh = g_vh + (size_t)bh * (KVLEN * HD);

    int ntile = causal ? (qt + 9) : 16;
    if (ntile > 16) ntile = 16;

    // Q tile (group 0)
#pragma unroll
    for (int i = 0; i < 8; i++) {
        int c = tid + i * 256;
        int row = c >> 4, kc = c & 15;
        cpa16(sb + row * 272 + kc * 16, Qh + (size_t)(qbase + row) * HD + kc * 8);
    }
    cpa_commit();
    // KV tiles 0 and 1 (groups 1, 2)
#pragma unroll
    for (int s = 0; s < 2; s++) {
        if (s < ntile) {
            const uint32_t st = sb + AKV + s * AKVSTG;
            const int kb0 = s * 128;
#pragma unroll
            for (int i = 0; i < 8; i++) {
                int c = tid + i * 256;
                int row = c >> 4, kc = c & 15;
                cpa16(st + row * 272 + kc * 16, Kh + (size_t)(kb0 + row) * HD + kc * 8);
                cpa16(st + AVOF + row * 272 + kc * 16, Vh + (size_t)(kb0 + row) * HD + kc * 8);
            }
            cpa_commit();
        }
    }
    cpa_wait2();                 // Q arrived
    __syncthreads();

    // Q fragments register-resident
    uint32_t qf[8][4];
    {
        const uint32_t qrow = (uint32_t)(w * 16 + (lane & 15)) * 272;
#pragma unroll
        for (int ks = 0; ks < 8; ks++)
            ldm4(qf[ks], sb + qrow + ks * 32 + (lane >> 4) * 16);
    }

    float oacc[16][4];
#pragma unroll
    for (int nq = 0; nq < 16; nq++)
#pragma unroll
        for (int e = 0; e < 4; e++) oacc[nq][e] = 0.f;
    float mrow[2] = {-1e30f, -1e30f}, lrow[2] = {0.f, 0.f};

    const float scale2 = 0.12751879523525493f;   // log2(e)/sqrt(128)
    const int roff = KVLEN - TQ;

    for (int kt = 0; kt < ntile; kt++) {
        if (kt + 1 < ntile) cpa_wait1(); else cpa_wait0();
        __syncthreads();                          // tile kt visible
        const uint32_t kvst = sb + AKV + (kt & 1) * AKVSTG;

        // ---- S = Q K^T ----
        float sacc[16][4];
#pragma unroll
        for (int nt = 0; nt < 16; nt++)
#pragma unroll
            for (int e = 0; e < 4; e++) sacc[nt][e] = 0.f;

        const uint32_t krow = (uint32_t)(lane & 15) * 272;
#pragma unroll
        for (int ks = 0; ks < 8; ks++) {
            const uint32_t koff = ks * 32 + (lane >> 4) * 16;
#pragma unroll
            for (int np = 0; np < 8; np++) {
                uint32_t kf[4];
                ldm4(kf, kvst + krow + np * 16 * 272 + koff);
                mma16816(sacc[2 * np],     qf[ks], kf[0], kf[2]);
                mma16816(sacc[2 * np + 1], qf[ks], kf[1], kf[3]);
            }
        }

        // ---- scale (log2 domain); causal mask under uniform branch ----
#pragma unroll
        for (int nt = 0; nt < 16; nt++)
#pragma unroll
            for (int e = 0; e < 4; e++) sacc[nt][e] *= scale2;
        if (causal) {
            const int kbase = kt * 128;
            const int rglo = qbase + w * 16 + (lane >> 2) + roff;
#pragma unroll
            for (int nt = 0; nt < 16; nt++)
#pragma unroll
                for (int e = 0; e < 4; e++) {
                    int cl = kbase + nt * 8 + (lane & 3) * 2 + (e & 1);
                    if (cl > rglo + (e >> 1) * 8) sacc[nt][e] = -1e30f;
                }
        }

        // ---- register softmax (quad shfl) ----
        float ml[2] = {-1e30f, -1e30f};
#pragma unroll
        for (int nt = 0; nt < 16; nt++) {
            ml[0] = fmaxf(ml[0], fmaxf(sacc[nt][0], sacc[nt][1]));
            ml[1] = fmaxf(ml[1], fmaxf(sacc[nt][2], sacc[nt][3]));
        }
#pragma unroll
        for (int i = 0; i < 2; i++) {
            ml[i] = fmaxf(ml[i], __shfl_xor_sync(0xffffffffu, ml[i], 1));
            ml[i] = fmaxf(ml[i], __shfl_xor_sync(0xffffffffu, ml[i], 2));
        }
        float mn[2], al[2];
#pragma unroll
        for (int i = 0; i < 2; i++) {
            mn[i] = fmaxf(mrow[i], ml[i]);
            al[i] = exp2f(mrow[i] - mn[i]);
            mrow[i] = mn[i];
        }

        // ---- P = exp2(S - m) packed fp16; directly PV A-fragments ----
        float ls[2] = {0.f, 0.f};
        uint32_t pf[8][4];
#pragma unroll
        for (int nt = 0; nt < 16; nt++) {
            uint32_t p01 = ex2h2(sacc[nt][0] - mn[0], sacc[nt][1] - mn[0]);
            uint32_t p23 = ex2h2(sacc[nt][2] - mn[1], sacc[nt][3] - mn[1]);
            pf[nt >> 1][(nt & 1) * 2 + 0] = p01;
            pf[nt >> 1][(nt & 1) * 2 + 1] = p23;
            float2 f0 = __half22float2(*(__half2*)&p01);
            float2 f1 = __half22float2(*(__half2*)&p23);
            ls[0] += f0.x + f0.y;
            ls[1] += f1.x + f1.y;
        }
#pragma unroll
        for (int i = 0; i < 2; i++) {
            ls[i] += __shfl_xor_sync(0xffffffffu, ls[i], 1);
            ls[i] += __shfl_xor_sync(0xffffffffu, ls[i], 2);
            lrow[i] = lrow[i] * al[i] + ls[i];
        }
#pragma unroll
        for (int nq = 0; nq < 16; nq++) {
            oacc[nq][0] *= al[0]; oacc[nq][1] *= al[0];
            oacc[nq][2] *= al[1]; oacc[nq][3] *= al[1];
        }

        // ---- O += P V ----
#pragma unroll
        for (int kp = 0; kp < 8; kp++) {
            const uint32_t vrow = (uint32_t)(kp * 16 + (lane & 15)) * 272 + (lane >> 4) * 16;
#pragma unroll
            for (int np = 0; np < 8; np++) {
                uint32_t vb[4];
                ldm4t(vb, kvst + AVOF + vrow + np * 32);
                mma16816(oacc[2 * np],     pf[kp], vb[0], vb[1]);
                mma16816(oacc[2 * np + 1], pf[kp], vb[2], vb[3]);
            }
        }
        __syncthreads();                          // all reads of buf kt&1 done

        if (kt + 2 < ntile) {                     // refill freed buffer
            const uint32_t st = sb + AKV + (kt & 1) * AKVSTG;
            const int kb0 = (kt + 2) * 128;
#pragma unroll
            for (int i = 0; i < 8; i++) {
                int c = tid + i * 256;
                int row = c >> 4, kc = c & 15;
                cpa16(st + row * 272 + kc * 16, Kh + (size_t)(kb0 + row) * HD + kc * 8);
                cpa16(st + AVOF + row * 272 + kc * 16, Vh + (size_t)(kb0 + row) * HD + kc * 8);
            }
            cpa_commit();
        }
    }

    // ---- epilogue: O / l -> fp16 y ----
#pragma unroll
    for (int i = 0; i < 2; i++) {
        float inv = 1.0f / lrow[i];
        int rl = w * 16 + (lane >> 2) + i * 8;
        __half* Yp = g_yh + (size_t)(b * TQ + qbase + rl) * D_MODEL + h * HD;
#pragma unroll
        for (int nq = 0; nq < 16; nq++) {
            int col = nq * 8 + (lane & 3) * 2;
            *(__half2*)(Yp + col) =
                __floats2half2_rn(oacc[nq][2 * i] * inv, oacc[nq][2 * i + 1] * inv);
        }
    }
}

// =====================================================================
// launch
// =====================================================================
extern "C" void kernel_launch(void* const* d_in, const int* in_sizes, int n_in,
                              void* d_out, int out_size)
{
    const float* x     = (const float*)d_in[0];
    const float* cosb  = (const float*)d_in[1];
    const float* sinb  = (const float*)d_in[2];
    const float* kxl   = (const float*)d_in[3];
    const float* vxl   = (const float*)d_in[4];
    const float* pos   = (const float*)d_in[5];
    const float* wqkv  = (const float*)d_in[6];
    const float* wproj = (const float*)d_in[7];
    const int*   flag  = (const int*)d_in[8];
    float*       out   = (float*)d_out;

    __half *ah, *bh, *bp, *yh;
    cudaGetSymbolAddress((void**)&ah, g_ah);
    cudaGetSymbolAddress((void**)&bh, g_bh);
    cudaGetSymbolAddress((void**)&bp, g_bp);
    cudaGetSymbolAddress((void**)&yh, g_yh);

    cudaFuncSetAttribute(attn_kernel, cudaFuncAttributeMaxDynamicSharedMemorySize, ATTN_SMEM);
    cudaFuncSetAttribute(gemm_mma<0>, cudaFuncAttributeMaxDynamicSharedMemorySize, GEMM_SMEM);
    cudaFuncSetAttribute(gemm_mma<1>, cudaFuncAttributeMaxDynamicSharedMemorySize, GEMM_SMEM);

    // 1) all conversions + XL prep, one segmented launch
    prep_kernel<<<28672, 256>>>(x, wqkv, wproj, kxl, vxl, pos);

    // 2) qkv GEMM with fused RoPE + q/k/v scatter (fp16 out)
    gemm_mma<1><<<dim3(3 * D_MODEL / 128, MROWS / 128), 256, GEMM_SMEM>>>(
        ah, bh, nullptr, cosb, sinb, MROWS, 3 * D_MODEL, D_MODEL);

    // 3) flash attention -> fp16 y
    attn_kernel<<<dim3(TQ / 128, BATCH * NHEADS), 256, ATTN_SMEM>>>(flag);

    // 4) out = y @ w_proj^T
    gemm_mma<0><<<dim3(D_MODEL / 128, MROWS / 128), 256, GEMM_SMEM>>>(
        yh, bp, out, nullptr, nullptr, MROWS, D_MODEL, D_MODEL);
}

// round 9
// speedup vs baseline: 6.6168x; 1.1048x over previous
#include <cuda_runtime.h>
#include <cuda_fp16.h>
#include <cstdint>

#define D_MODEL 2048
#define NHEADS  16
#define HD      128
#define BATCH   2
#define TQ      1024
#define XLLEN   1024
#define KVLEN   2048
#define MROWS   (BATCH * TQ)    // 2048

// ---------------- scratch (device globals) ----------------
__device__ __half g_yh [(size_t)MROWS * D_MODEL];
__device__ __half g_qh [(size_t)BATCH * NHEADS * TQ * HD];
__device__ __half g_kh [(size_t)BATCH * NHEADS * KVLEN * HD];
__device__ __half g_vh [(size_t)BATCH * NHEADS * KVLEN * HD];
__device__ __half g_ah [(size_t)MROWS * D_MODEL];
__device__ __half g_bh [(size_t)3 * D_MODEL * D_MODEL];
__device__ __half g_bp [(size_t)D_MODEL * D_MODEL];

// ======================= PTX helpers =======================
__device__ __forceinline__ uint32_t smem_u32(const void* p) {
    uint32_t a;
    asm("{ .reg .u64 t; cvta.to.shared.u64 t, %1; cvt.u32.u64 %0, t; }" : "=r"(a) : "l"(p));
    return a;
}
__device__ __forceinline__ void ldm4(uint32_t* r, uint32_t a) {
    asm volatile("ldmatrix.sync.aligned.m8n8.x4.shared.b16 {%0,%1,%2,%3}, [%4];"
                 : "=r"(r[0]), "=r"(r[1]), "=r"(r[2]), "=r"(r[3]) : "r"(a));
}
__device__ __forceinline__ void ldm4t(uint32_t* r, uint32_t a) {
    asm volatile("ldmatrix.sync.aligned.m8n8.x4.trans.shared.b16 {%0,%1,%2,%3}, [%4];"
                 : "=r"(r[0]), "=r"(r[1]), "=r"(r[2]), "=r"(r[3]) : "r"(a));
}
__device__ __forceinline__ void mma16816(float* d, const uint32_t* a, uint32_t b0, uint32_t b1) {
    asm volatile("mma.sync.aligned.m16n8k16.row.col.f32.f16.f16.f32 "
                 "{%0,%1,%2,%3}, {%4,%5,%6,%7}, {%8,%9}, {%0,%1,%2,%3};"
                 : "+f"(d[0]), "+f"(d[1]), "+f"(d[2]), "+f"(d[3])
                 : "r"(a[0]), "r"(a[1]), "r"(a[2]), "r"(a[3]), "r"(b0), "r"(b1));
}
__device__ __forceinline__ void cpa16(uint32_t dst, const void* src) {
    asm volatile("cp.async.cg.shared.global [%0], [%1], 16;" :: "r"(dst), "l"(src));
}
__device__ __forceinline__ void cpa_commit() { asm volatile("cp.async.commit_group;" ::: "memory"); }
__device__ __forceinline__ void cpa_wait2()  { asm volatile("cp.async.wait_group 2;" ::: "memory"); }
__device__ __forceinline__ void cpa_wait1()  { asm volatile("cp.async.wait_group 1;" ::: "memory"); }
__device__ __forceinline__ void cpa_wait0()  { asm volatile("cp.async.wait_group 0;" ::: "memory"); }
// packed-half exp2: one MUFU op for two values; results are P fragments
__device__ __forceinline__ uint32_t ex2h2(float a, float b) {
    __half2 t = __floats2half2_rn(a, b);
    uint32_t u = *(uint32_t*)&t, r;
    asm("ex2.approx.f16x2 %0, %1;" : "=r"(r) : "r"(u));
    return r;
}
__device__ __forceinline__ uint4 cvt8(float4 a, float4 b) {
    __half h[8] = {__float2half_rn(a.x), __float2half_rn(a.y),
                   __float2half_rn(a.z), __float2half_rn(a.w),
                   __float2half_rn(b.x), __float2half_rn(b.y),
                   __float2half_rn(b.z), __float2half_rn(b.w)};
    return *(uint4*)h;
}

// =====================================================================
// prep: fp32->fp16 conversions + XL K/V prep; 8 elems / thread,
// fully-coalesced 32B reads / 16B writes.  12288 blocks x 256.
// =====================================================================
__global__ void prep_kernel(const float* __restrict__ x, const float* __restrict__ wqkv,
                            const float* __restrict__ wproj, const float* __restrict__ kxl,
                            const float* __restrict__ vxl, const float* __restrict__ pos)
{
    const int blk = blockIdx.x;
    if (blk < 10240) {
        const float* src; __half* dst; int i;
        if (blk < 2048)      { src = x;     dst = g_ah; i = blk * 256 + threadIdx.x; }
        else if (blk < 8192) { src = wqkv;  dst = g_bh; i = (blk - 2048) * 256 + threadIdx.x; }
        else                 { src = wproj; dst = g_bp; i = (blk - 8192) * 256 + threadIdx.x; }
        float4 v0 = ((const float4*)src)[2 * i];
        float4 v1 = ((const float4*)src)[2 * i + 1];
        *(uint4*)(dst + (size_t)i * 8) = cvt8(v0, v1);
    } else {
        int idx = (blk - 10240) * 256 + threadIdx.x;   // (b, t, h, d8)
        int d8 = idx & 15;
        int h  = (idx >> 4) & 15;
        int t  = (idx >> 8) & 1023;
        int b  = idx >> 18;
        size_t src = ((size_t)(b * XLLEN + t)) * D_MODEL + h * HD + d8 * 8;
        size_t ps  = (size_t)t * D_MODEL + h * HD + d8 * 8;
        float4 k0 = *(const float4*)(kxl + src), k1 = *(const float4*)(kxl + src + 4);
        float4 p0 = *(const float4*)(pos + ps),  p1 = *(const float4*)(pos + ps + 4);
        float4 v0 = *(const float4*)(vxl + src), v1 = *(const float4*)(vxl + src + 4);
        k0.x += p0.x; k0.y += p0.y; k0.z += p0.z; k0.w += p0.w;
        k1.x += p1.x; k1.y += p1.y; k1.z += p1.z; k1.w += p1.w;
        size_t dst = ((size_t)((b * NHEADS + h) * KVLEN + t)) * HD + d8 * 8;
        *(uint4*)&g_kh[dst] = cvt8(k0, k1);
        *(uint4*)&g_vh[dst] = cvt8(v0, v1);
    }
}

// =====================================================================
// fp16 mma.sync NT GEMM: 128x128 CTA tile, BK=32, 8 warps (64x32),
// 4-stage cp.async ring, prefetch distance 2, ONE barrier per K-block.
// MODE 0: fp32 C.  MODE 1: fused RoPE + q/k/v scatter epilogue.
// =====================================================================
#define GTILE_B  10240            // 128 rows x 80B
#define GSTG_B   (2 * GTILE_B)    // A + B
#define GEMM_SMEM (4 * GSTG_B)    // 81920

template<int MODE>
__global__ __launch_bounds__(256, 2) void gemm_mma(
    const __half* __restrict__ A, const __half* __restrict__ B,
    float* __restrict__ C, const float* __restrict__ cosb, const float* __restrict__ sinb,
    int M, int N, int K)
{
    extern __shared__ __align__(16) char smraw[];
    const uint32_t sb = smem_u32(smraw);
    const int tid = threadIdx.x, wid = tid >> 5, lane = tid & 31;
    const int wm = wid & 1, wn = wid >> 1;
    const int mb = blockIdx.y * 128, nb = blockIdx.x * 128;

    const __half* Asrc = A + (size_t)mb * K;
    const __half* Bsrc = B + (size_t)nb * K;
    const int NKB = K >> 5;
    const int lrow = tid >> 2, lkc = (tid & 3);

    // prologue: stages 0, 1 (prefetch distance 2)
#pragma unroll
    for (int s = 0; s < 2; s++) {
        const uint32_t st = sb + s * GSTG_B;
        const int ko = s * 32;
#pragma unroll
        for (int i = 0; i < 2; i++) {
            int row = lrow + i * 64;
            cpa16(st + row * 80 + lkc * 16, Asrc + (size_t)row * K + ko + lkc * 8);
            cpa16(st + GTILE_B + row * 80 + lkc * 16, Bsrc + (size_t)row * K + ko + lkc * 8);
        }
        cpa_commit();
    }

    float acc[4][4][4];
#pragma unroll
    for (int a = 0; a < 4; a++)
#pragma unroll
        for (int b = 0; b < 4; b++)
#pragma unroll
            for (int e = 0; e < 4; e++) acc[a][b][e] = 0.f;

    const uint32_t arow = (uint32_t)(wm * 64 + (lane & 15)) * 80;
    const uint32_t brow = (uint32_t)(wn * 32 + (lane & 15)) * 80;
    const uint32_t lhalf = (lane >> 4) * 16;

    for (int kb = 0; kb < NKB; kb++) {
        if (kb + 2 < NKB) cpa_wait1(); else cpa_wait0();
        __syncthreads();                               // single barrier per K-block
        const uint32_t st = sb + (kb & 3) * GSTG_B;

        // ---- ks0 fragment loads ----
        uint32_t Af[4][4], Bf[2][4];
#pragma unroll
        for (int mt = 0; mt < 4; mt++)
            ldm4(Af[mt], st + arow + mt * 16 * 80 + lhalf);
#pragma unroll
        for (int np = 0; np < 2; np++)
            ldm4(Bf[np], st + GTILE_B + brow + np * 16 * 80 + lhalf);

        // ---- prefetch stage kb+2 (LSU work overlaps LDS latency) ----
        if (kb + 2 < NKB) {
            const uint32_t pst = sb + ((kb + 2) & 3) * GSTG_B;
            const int ko = (kb + 2) * 32;
#pragma unroll
            for (int i = 0; i < 2; i++) {
                int row = lrow + i * 64;
                cpa16(pst + row * 80 + lkc * 16, Asrc + (size_t)row * K + ko + lkc * 8);
                cpa16(pst + GTILE_B + row * 80 + lkc * 16, Bsrc + (size_t)row * K + ko + lkc * 8);
            }
            cpa_commit();
        }

        // ---- mma ks0 ----
#pragma unroll
        for (int mt = 0; mt < 4; mt++)
#pragma unroll
            for (int nt = 0; nt < 4; nt++)
                mma16816(acc[mt][nt], Af[mt], Bf[nt >> 1][nt & 1], Bf[nt >> 1][(nt & 1) + 2]);

        // ---- ks1 fragment loads + mma ----
#pragma unroll
        for (int mt = 0; mt < 4; mt++)
            ldm4(Af[mt], st + arow + mt * 16 * 80 + 32 + lhalf);
#pragma unroll
        for (int np = 0; np < 2; np++)
            ldm4(Bf[np], st + GTILE_B + brow + np * 16 * 80 + 32 + lhalf);
#pragma unroll
        for (int mt = 0; mt < 4; mt++)
#pragma unroll
            for (int nt = 0; nt < 4; nt++)
                mma16816(acc[mt][nt], Af[mt], Bf[nt >> 1][nt & 1], Bf[nt >> 1][(nt & 1) + 2]);
    }

    if (MODE == 0) {
#pragma unroll
        for (int mt = 0; mt < 4; mt++) {
            int row0 = mb + wm * 64 + mt * 16 + (lane >> 2);
#pragma unroll
            for (int nt = 0; nt < 4; nt++) {
                int col = nb + wn * 32 + nt * 8 + (lane & 3) * 2;
                *(float2*)&C[(size_t)row0 * N + col]       = make_float2(acc[mt][nt][0], acc[mt][nt][1]);
                *(float2*)&C[(size_t)(row0 + 8) * N + col] = make_float2(acc[mt][nt][2], acc[mt][nt][3]);
            }
        }
    } else {
        // fused RoPE + scatter; region (q/k/v) and head are CTA-uniform.
        const int region = nb >> 11;
        const int hh = (nb & 2047) >> 7;
#pragma unroll
        for (int mt = 0; mt < 4; mt++) {
#pragma unroll
            for (int i = 0; i < 2; i++) {
                int row = mb + wm * 64 + mt * 16 + (lane >> 2) + i * 8;
                int bb = row >> 10, t = row & 1023;
#pragma unroll
                for (int nt = 0; nt < 4; nt++) {
                    int d = wn * 32 + nt * 8 + (lane & 3) * 2;
                    float a0 = acc[mt][nt][2 * i], a1 = acc[mt][nt][2 * i + 1];
                    if (region == 2) {
                        size_t dst = ((size_t)(bb * NHEADS + hh) * KVLEN + XLLEN + t) * HD + d;
                        *(__half2*)&g_vh[dst] = __floats2half2_rn(a0, a1);
                    } else {
                        int dp = d >> 1;
                        float cv = cosb[t * 64 + dp], sv = sinb[t * 64 + dp];
                        float o0 = a0 * cv - a1 * sv;
                        float o1 = a0 * sv + a1 * cv;
                        if (region == 0) {
                            size_t dst = ((size_t)(bb * NHEADS + hh) * TQ + t) * HD + d;
                            *(__half2*)&g_qh[dst] = __floats2half2_rn(o0, o1);
                        } else {
                            size_t dst = ((size_t)(bb * NHEADS + hh) * KVLEN + XLLEN + t) * HD + d;
                            *(__half2*)&g_kh[dst] = __floats2half2_rn(o0, o1);
                        }
                    }
                }
            }
        }
    }
}

// =====================================================================
// Flash attention FA2: BQ=128, BK=128, D=128, 8 warps, 2-stage KV.
// softmax exp via ex2.approx.f16x2; P fragments straight from S regs.
// =====================================================================
#define AQSZ   34816                      // 128 rows x 272B
#define AKV    AQSZ
#define AKVSTG 69632                      // K(128x272) + V(128x272)
#define AVOF   34816
#define ATTN_SMEM (AQSZ + 2 * AKVSTG)     // 174080

__global__ __launch_bounds__(256) void attn_kernel(const int* __restrict__ flag)
{
    extern __shared__ __align__(16) char smraw[];
    const uint32_t sb = smem_u32(smraw);
    const int tid = threadIdx.x, w = tid >> 5, lane = tid & 31;
    const int qt = blockIdx.x, bh = blockIdx.y;
    const int b = bh >> 4, h = bh & 15;
    const int qbase = qt * 128;
    const int causal = *flag;

    const __half* Qh = g_qh + (size_t)bh * (TQ * HD);
    const __half* Kh = g_kh + (size_t)bh * (KVLEN * HD);
    const __half* Vh = g_vh + (size_t)bh * (KVLEN * HD);

    int ntile = causal ? (qt + 9) : 16;
    if (ntile > 16) ntile = 16;

    // Q tile (group 0)
#pragma unroll
    for (int i = 0; i < 8; i++) {
        int c = tid + i * 256;
        int row = c >> 4, kc = c & 15;
        cpa16(sb + row * 272 + kc * 16, Qh + (size_t)(qbase + row) * HD + kc * 8);
    }
    cpa_commit();
    // KV tiles 0 and 1 (groups 1, 2)
#pragma unroll
    for (int s = 0; s < 2; s++) {
        if (s < ntile) {
            const uint32_t st = sb + AKV + s * AKVSTG;
            const int kb0 = s * 128;
#pragma unroll
            for (int i = 0; i < 8; i++) {
                int c = tid + i * 256;
                int row = c >> 4, kc = c & 15;
                cpa16(st + row * 272 + kc * 16, Kh + (size_t)(kb0 + row) * HD + kc * 8);
                cpa16(st + AVOF + row * 272 + kc * 16, Vh + (size_t)(kb0 + row) * HD + kc * 8);
            }
            cpa_commit();
        }
    }
    cpa_wait2();                 // Q arrived
    __syncthreads();

    // Q fragments register-resident
    uint32_t qf[8][4];
    {
        const uint32_t qrow = (uint32_t)(w * 16 + (lane & 15)) * 272;
#pragma unroll
        for (int ks = 0; ks < 8; ks++)
            ldm4(qf[ks], sb + qrow + ks * 32 + (lane >> 4) * 16);
    }

    float oacc[16][4];
#pragma unroll
    for (int nq = 0; nq < 16; nq++)
#pragma unroll
        for (int e = 0; e < 4; e++) oacc[nq][e] = 0.f;
    float mrow[2] = {-1e30f, -1e30f}, lrow[2] = {0.f, 0.f};

    const float scale2 = 0.12751879523525493f;   // log2(e)/sqrt(128)
    const int roff = KVLEN - TQ;

    for (int kt = 0; kt < ntile; kt++) {
        if (kt + 1 < ntile) cpa_wait1(); else cpa_wait0();
        __syncthreads();                          // tile kt visible
        const uint32_t kvst = sb + AKV + (kt & 1) * AKVSTG;

        // ---- S = Q K^T ----
        float sacc[16][4];
#pragma unroll
        for (int nt = 0; nt < 16; nt++)
#pragma unroll
            for (int e = 0; e < 4; e++) sacc[nt][e] = 0.f;

        const uint32_t krow = (uint32_t)(lane & 15) * 272;
#pragma unroll
        for (int ks = 0; ks < 8; ks++) {
            const uint32_t koff = ks * 32 + (lane >> 4) * 16;
#pragma unroll
            for (int np = 0; np < 8; np++) {
                uint32_t kf[4];
                ldm4(kf, kvst + krow + np * 16 * 272 + koff);
                mma16816(sacc[2 * np],     qf[ks], kf[0], kf[2]);
                mma16816(sacc[2 * np + 1], qf[ks], kf[1], kf[3]);
            }
        }

        // ---- scale (log2 domain); causal mask under uniform branch ----
#pragma unroll
        for (int nt = 0; nt < 16; nt++)
#pragma unroll
            for (int e = 0; e < 4; e++) sacc[nt][e] *= scale2;
        if (causal) {
            const int kbase = kt * 128;
            const int rglo = qbase + w * 16 + (lane >> 2) + roff;
#pragma unroll
            for (int nt = 0; nt < 16; nt++)
#pragma unroll
                for (int e = 0; e < 4; e++) {
                    int cl = kbase + nt * 8 + (lane & 3) * 2 + (e & 1);
                    if (cl > rglo + (e >> 1) * 8) sacc[nt][e] = -1e30f;
                }
        }

        // ---- register softmax (quad shfl) ----
        float ml[2] = {-1e30f, -1e30f};
#pragma unroll
        for (int nt = 0; nt < 16; nt++) {
            ml[0] = fmaxf(ml[0], fmaxf(sacc[nt][0], sacc[nt][1]));
            ml[1] = fmaxf(ml[1], fmaxf(sacc[nt][2], sacc[nt][3]));
        }
#pragma unroll
        for (int i = 0; i < 2; i++) {
            ml[i] = fmaxf(ml[i], __shfl_xor_sync(0xffffffffu, ml[i], 1));
            ml[i] = fmaxf(ml[i], __shfl_xor_sync(0xffffffffu, ml[i], 2));
        }
        float mn[2], al[2];
#pragma unroll
        for (int i = 0; i < 2; i++) {
            mn[i] = fmaxf(mrow[i], ml[i]);
            al[i] = exp2f(mrow[i] - mn[i]);
            mrow[i] = mn[i];
        }

        // ---- P = exp2(S - m) packed fp16; directly PV A-fragments ----
        float ls[2] = {0.f, 0.f};
        uint32_t pf[8][4];
#pragma unroll
        for (int nt = 0; nt < 16; nt++) {
            uint32_t p01 = ex2h2(sacc[nt][0] - mn[0], sacc[nt][1] - mn[0]);
            uint32_t p23 = ex2h2(sacc[nt][2] - mn[1], sacc[nt][3] - mn[1]);
            pf[nt >> 1][(nt & 1) * 2 + 0] = p01;
            pf[nt >> 1][(nt & 1) * 2 + 1] = p23;
            float2 f0 = __half22float2(*(__half2*)&p01);
            float2 f1 = __half22float2(*(__half2*)&p23);
            ls[0] += f0.x + f0.y;
            ls[1] += f1.x + f1.y;
        }
#pragma unroll
        for (int i = 0; i < 2; i++) {
            ls[i] += __shfl_xor_sync(0xffffffffu, ls[i], 1);
            ls[i] += __shfl_xor_sync(0xffffffffu, ls[i], 2);
            lrow[i] = lrow[i] * al[i] + ls[i];
        }
#pragma unroll
        for (int nq = 0; nq < 16; nq++) {
            oacc[nq][0] *= al[0]; oacc[nq][1] *= al[0];
            oacc[nq][2] *= al[1]; oacc[nq][3] *= al[1];
        }

        // ---- O += P V ----
#pragma unroll
        for (int kp = 0; kp < 8; kp++) {
            const uint32_t vrow = (uint32_t)(kp * 16 + (lane & 15)) * 272 + (lane >> 4) * 16;
#pragma unroll
            for (int np = 0; np < 8; np++) {
                uint32_t vb[4];
                ldm4t(vb, kvst + AVOF + vrow + np * 32);
                mma16816(oacc[2 * np],     pf[kp], vb[0], vb[1]);
                mma16816(oacc[2 * np + 1], pf[kp], vb[2], vb[3]);
            }
        }
        __syncthreads();                          // all reads of buf kt&1 done

        if (kt + 2 < ntile) {                     // refill freed buffer
            const uint32_t st = sb + AKV + (kt & 1) * AKVSTG;
            const int kb0 = (kt + 2) * 128;
#pragma unroll
            for (int i = 0; i < 8; i++) {
                int c = tid + i * 256;
                int row = c >> 4, kc = c & 15;
                cpa16(st + row * 272 + kc * 16, Kh + (size_t)(kb0 + row) * HD + kc * 8);
                cpa16(st + AVOF + row * 272 + kc * 16, Vh + (size_t)(kb0 + row) * HD + kc * 8);
            }
            cpa_commit();
        }
    }

    // ---- epilogue: O / l -> fp16 y ----
#pragma unroll
    for (int i = 0; i < 2; i++) {
        float inv = 1.0f / lrow[i];
        int rl = w * 16 + (lane >> 2) + i * 8;
        __half* Yp = g_yh + (size_t)(b * TQ + qbase + rl) * D_MODEL + h * HD;
#pragma unroll
        for (int nq = 0; nq < 16; nq++) {
            int col = nq * 8 + (lane & 3) * 2;
            *(__half2*)(Yp + col) =
                __floats2half2_rn(oacc[nq][2 * i] * inv, oacc[nq][2 * i + 1] * inv);
        }
    }
}

// =====================================================================
// launch
// =====================================================================
extern "C" void kernel_launch(void* const* d_in, const int* in_sizes, int n_in,
                              void* d_out, int out_size)
{
    const float* x     = (const float*)d_in[0];
    const float* cosb  = (const float*)d_in[1];
    const float* sinb  = (const float*)d_in[2];
    const float* kxl   = (const float*)d_in[3];
    const float* vxl   = (const float*)d_in[4];
    const float* pos   = (const float*)d_in[5];
    const float* wqkv  = (const float*)d_in[6];
    const float* wproj = (const float*)d_in[7];
    const int*   flag  = (const int*)d_in[8];
    float*       out   = (float*)d_out;

    __half *ah, *bh, *bp, *yh;
    cudaGetSymbolAddress((void**)&ah, g_ah);
    cudaGetSymbolAddress((void**)&bh, g_bh);
    cudaGetSymbolAddress((void**)&bp, g_bp);
    cudaGetSymbolAddress((void**)&yh, g_yh);

    cudaFuncSetAttribute(attn_kernel, cudaFuncAttributeMaxDynamicSharedMemorySize, ATTN_SMEM);
    cudaFuncSetAttribute(gemm_mma<0>, cudaFuncAttributeMaxDynamicSharedMemorySize, GEMM_SMEM);
    cudaFuncSetAttribute(gemm_mma<1>, cudaFuncAttributeMaxDynamicSharedMemorySize, GEMM_SMEM);

    // 1) all conversions + XL prep, one segmented launch
    prep_kernel<<<12288, 256>>>(x, wqkv, wproj, kxl, vxl, pos);

    // 2) qkv GEMM with fused RoPE + q/k/v scatter (fp16 out)
    gemm_mma<1><<<dim3(3 * D_MODEL / 128, MROWS / 128), 256, GEMM_SMEM>>>(
        ah, bh, nullptr, cosb, sinb, MROWS, 3 * D_MODEL, D_MODEL);

    // 3) flash attention -> fp16 y
    attn_kernel<<<dim3(TQ / 128, BATCH * NHEADS), 256, ATTN_SMEM>>>(flag);

    // 4) out = y @ w_proj^T
    gemm_mma<0><<<dim3(D_MODEL / 128, MROWS / 128), 256, GEMM_SMEM>>>(
        yh, bp, out, nullptr, nullptr, MROWS, D_MODEL, D_MODEL);
}

// round 10
// speedup vs baseline: 6.6230x; 1.0009x over previous
#include <cuda_runtime.h>
#include <cuda_fp16.h>
#include <cstdint>

#define D_MODEL 2048
#define NHEADS  16
#define HD      128
#define BATCH   2
#define TQ      1024
#define XLLEN   1024
#define KVLEN   2048
#define MROWS   (BATCH * TQ)    // 2048

// ---------------- scratch (device globals) ----------------
__device__ __half g_yh [(size_t)MROWS * D_MODEL];
__device__ __half g_qh [(size_t)BATCH * NHEADS * TQ * HD];
__device__ __half g_kh [(size_t)BATCH * NHEADS * KVLEN * HD];
__device__ __half g_vh [(size_t)BATCH * NHEADS * KVLEN * HD];
__device__ __half g_ah [(size_t)MROWS * D_MODEL];
__device__ __half g_bh [(size_t)3 * D_MODEL * D_MODEL];
__device__ __half g_bp [(size_t)D_MODEL * D_MODEL];

// ======================= PTX helpers =======================
__device__ __forceinline__ uint32_t smem_u32(const void* p) {
    uint32_t a;
    asm("{ .reg .u64 t; cvta.to.shared.u64 t, %1; cvt.u32.u64 %0, t; }" : "=r"(a) : "l"(p));
    return a;
}
__device__ __forceinline__ void ldm4(uint32_t* r, uint32_t a) {
    asm volatile("ldmatrix.sync.aligned.m8n8.x4.shared.b16 {%0,%1,%2,%3}, [%4];"
                 : "=r"(r[0]), "=r"(r[1]), "=r"(r[2]), "=r"(r[3]) : "r"(a));
}
__device__ __forceinline__ void ldm4t(uint32_t* r, uint32_t a) {
    asm volatile("ldmatrix.sync.aligned.m8n8.x4.trans.shared.b16 {%0,%1,%2,%3}, [%4];"
                 : "=r"(r[0]), "=r"(r[1]), "=r"(r[2]), "=r"(r[3]) : "r"(a));
}
__device__ __forceinline__ void mma16816(float* d, const uint32_t* a, uint32_t b0, uint32_t b1) {
    asm volatile("mma.sync.aligned.m16n8k16.row.col.f32.f16.f16.f32 "
                 "{%0,%1,%2,%3}, {%4,%5,%6,%7}, {%8,%9}, {%0,%1,%2,%3};"
                 : "+f"(d[0]), "+f"(d[1]), "+f"(d[2]), "+f"(d[3])
                 : "r"(a[0]), "r"(a[1]), "r"(a[2]), "r"(a[3]), "r"(b0), "r"(b1));
}
__device__ __forceinline__ void cpa16(uint32_t dst, const void* src) {
    asm volatile("cp.async.cg.shared.global [%0], [%1], 16;" :: "r"(dst), "l"(src));
}
__device__ __forceinline__ void cpa_commit() { asm volatile("cp.async.commit_group;" ::: "memory"); }
__device__ __forceinline__ void cpa_wait1()  { asm volatile("cp.async.wait_group 1;" ::: "memory"); }
__device__ __forceinline__ void cpa_wait0()  { asm volatile("cp.async.wait_group 0;" ::: "memory"); }
// packed-half exp2: one MUFU op for two values; results are P fragments
__device__ __forceinline__ uint32_t ex2h2(float a, float b) {
    __half2 t = __floats2half2_rn(a, b);
    uint32_t u = *(uint32_t*)&t, r;
    asm("ex2.approx.f16x2 %0, %1;" : "=r"(r) : "r"(u));
    return r;
}
__device__ __forceinline__ uint4 cvt8(float4 a, float4 b) {
    __half h[8] = {__float2half_rn(a.x), __float2half_rn(a.y),
                   __float2half_rn(a.z), __float2half_rn(a.w),
                   __float2half_rn(b.x), __float2half_rn(b.y),
                   __float2half_rn(b.z), __float2half_rn(b.w)};
    return *(uint4*)h;
}

// =====================================================================
// prep1: fp32->fp16 for x + wqkv ONLY (the qkv GEMM's inputs).
// wproj conversion + XL prep ride inside the qkv GEMM grid (aux CTAs).
// =====================================================================
__global__ void prep1_kernel(const float* __restrict__ x, const float* __restrict__ wqkv)
{
    const int blk = blockIdx.x;
    const float* src; __half* dst; int i;
    if (blk < 2048) { src = x;    dst = g_ah; i = blk * 256 + threadIdx.x; }
    else            { src = wqkv; dst = g_bh; i = (blk - 2048) * 256 + threadIdx.x; }
    float4 v0 = ((const float4*)src)[2 * i];
    float4 v1 = ((const float4*)src)[2 * i + 1];
    *(uint4*)(dst + (size_t)i * 8) = cvt8(v0, v1);
}

// =====================================================================
// fp16 mma.sync NT GEMM: 128x128 CTA tile, BK=32, 8 warps (64x32),
// 4-stage cp.async ring, prefetch distance 2, ONE barrier per K-block.
// MODE 0: fp32 C.
// MODE 1: fused RoPE + q/k/v scatter epilogue; blockIdx.y==16 CTAs are
//         aux workers (wproj conversion + XL K/V prep) overlapped with
//         the tensor-bound GEMM CTAs.
// =====================================================================
#define GTILE_B  10240            // 128 rows x 80B
#define GSTG_B   (2 * GTILE_B)    // A + B
#define GEMM_SMEM (4 * GSTG_B)    // 81920

#define AUX_NW   (D_MODEL * D_MODEL / 8)               // wproj units
#define AUX_NX   (BATCH * XLLEN * D_MODEL / 8)         // XL units
#define AUX_THREADS (48 * 256)

template<int MODE>
__global__ __launch_bounds__(256, 2) void gemm_mma(
    const __half* __restrict__ A, const __half* __restrict__ B,
    float* __restrict__ C, const float* __restrict__ cosb, const float* __restrict__ sinb,
    const float* __restrict__ wproj, const float* __restrict__ kxl,
    const float* __restrict__ vxl, const float* __restrict__ pos,
    int M, int N, int K)
{
    if (MODE == 1 && blockIdx.y == 16) {
        // ---- aux CTAs: wproj fp32->fp16 + XL K/V prep ----
        int tg = blockIdx.x * 256 + threadIdx.x;    // 0..12287
        for (int u = tg; u < AUX_NW + AUX_NX; u += AUX_THREADS) {
            if (u < AUX_NW) {
                float4 v0 = ((const float4*)wproj)[2 * u];
                float4 v1 = ((const float4*)wproj)[2 * u + 1];
                *(uint4*)(g_bp + (size_t)u * 8) = cvt8(v0, v1);
            } else {
                int idx = u - AUX_NW;                // (b, t, h, d8)
                int d8 = idx & 15;
                int h  = (idx >> 4) & 15;
                int t  = (idx >> 8) & 1023;
                int b  = idx >> 18;
                size_t src = ((size_t)(b * XLLEN + t)) * D_MODEL + h * HD + d8 * 8;
                size_t ps  = (size_t)t * D_MODEL + h * HD + d8 * 8;
                float4 k0 = *(const float4*)(kxl + src), k1 = *(const float4*)(kxl + src + 4);
                float4 p0 = *(const float4*)(pos + ps),  p1 = *(const float4*)(pos + ps + 4);
                float4 v0 = *(const float4*)(vxl + src), v1 = *(const float4*)(vxl + src + 4);
                k0.x += p0.x; k0.y += p0.y; k0.z += p0.z; k0.w += p0.w;
                k1.x += p1.x; k1.y += p1.y; k1.z += p1.z; k1.w += p1.w;
                size_t dst = ((size_t)((b * NHEADS + h) * KVLEN + t)) * HD + d8 * 8;
                *(uint4*)&g_kh[dst] = cvt8(k0, k1);
                *(uint4*)&g_vh[dst] = cvt8(v0, v1);
            }
        }
        return;
    }

    extern __shared__ __align__(16) char smraw[];
    const uint32_t sb = smem_u32(smraw);
    const int tid = threadIdx.x, wid = tid >> 5, lane = tid & 31;
    const int wm = wid & 1, wn = wid >> 1;
    const int mb = blockIdx.y * 128, nb = blockIdx.x * 128;

    const __half* Asrc = A + (size_t)mb * K;
    const __half* Bsrc = B + (size_t)nb * K;
    const int NKB = K >> 5;
    const int lrow = tid >> 2, lkc = (tid & 3);

    // prologue: stages 0, 1 (prefetch distance 2)
#pragma unroll
    for (int s = 0; s < 2; s++) {
        const uint32_t st = sb + s * GSTG_B;
        const int ko = s * 32;
#pragma unroll
        for (int i = 0; i < 2; i++) {
            int row = lrow + i * 64;
            cpa16(st + row * 80 + lkc * 16, Asrc + (size_t)row * K + ko + lkc * 8);
            cpa16(st + GTILE_B + row * 80 + lkc * 16, Bsrc + (size_t)row * K + ko + lkc * 8);
        }
        cpa_commit();
    }

    float acc[4][4][4];
#pragma unroll
    for (int a = 0; a < 4; a++)
#pragma unroll
        for (int b = 0; b < 4; b++)
#pragma unroll
            for (int e = 0; e < 4; e++) acc[a][b][e] = 0.f;

    const uint32_t arow = (uint32_t)(wm * 64 + (lane & 15)) * 80;
    const uint32_t brow = (uint32_t)(wn * 32 + (lane & 15)) * 80;
    const uint32_t lhalf = (lane >> 4) * 16;

    for (int kb = 0; kb < NKB; kb++) {
        if (kb + 2 < NKB) cpa_wait1(); else cpa_wait0();
        __syncthreads();                               // single barrier per K-block
        const uint32_t st = sb + (kb & 3) * GSTG_B;

        // ---- ks0 fragment loads ----
        uint32_t Af[4][4], Bf[2][4];
#pragma unroll
        for (int mt = 0; mt < 4; mt++)
            ldm4(Af[mt], st + arow + mt * 16 * 80 + lhalf);
#pragma unroll
        for (int np = 0; np < 2; np++)
            ldm4(Bf[np], st + GTILE_B + brow + np * 16 * 80 + lhalf);

        // ---- prefetch stage kb+2 (LSU work overlaps LDS latency) ----
        if (kb + 2 < NKB) {
            const uint32_t pst = sb + ((kb + 2) & 3) * GSTG_B;
            const int ko = (kb + 2) * 32;
#pragma unroll
            for (int i = 0; i < 2; i++) {
                int row = lrow + i * 64;
                cpa16(pst + row * 80 + lkc * 16, Asrc + (size_t)row * K + ko + lkc * 8);
                cpa16(pst + GTILE_B + row * 80 + lkc * 16, Bsrc + (size_t)row * K + ko + lkc * 8);
            }
            cpa_commit();
        }

        // ---- mma ks0 ----
#pragma unroll
        for (int mt = 0; mt < 4; mt++)
#pragma unroll
            for (int nt = 0; nt < 4; nt++)
                mma16816(acc[mt][nt], Af[mt], Bf[nt >> 1][nt & 1], Bf[nt >> 1][(nt & 1) + 2]);

        // ---- ks1 fragment loads + mma ----
#pragma unroll
        for (int mt = 0; mt < 4; mt++)
            ldm4(Af[mt], st + arow + mt * 16 * 80 + 32 + lhalf);
#pragma unroll
        for (int np = 0; np < 2; np++)
            ldm4(Bf[np], st + GTILE_B + brow + np * 16 * 80 + 32 + lhalf);
#pragma unroll
        for (int mt = 0; mt < 4; mt++)
#pragma unroll
            for (int nt = 0; nt < 4; nt++)
                mma16816(acc[mt][nt], Af[mt], Bf[nt >> 1][nt & 1], Bf[nt >> 1][(nt & 1) + 2]);
    }

    if (MODE == 0) {
#pragma unroll
        for (int mt = 0; mt < 4; mt++) {
            int row0 = mb + wm * 64 + mt * 16 + (lane >> 2);
#pragma unroll
            for (int nt = 0; nt < 4; nt++) {
                int col = nb + wn * 32 + nt * 8 + (lane & 3) * 2;
                *(float2*)&C[(size_t)row0 * N + col]       = make_float2(acc[mt][nt][0], acc[mt][nt][1]);
                *(float2*)&C[(size_t)(row0 + 8) * N + col] = make_float2(acc[mt][nt][2], acc[mt][nt][3]);
            }
        }
    } else {
        // fused RoPE + scatter; region (q/k/v) and head are CTA-uniform.
        const int region = nb >> 11;
        const int hh = (nb & 2047) >> 7;
#pragma unroll
        for (int mt = 0; mt < 4; mt++) {
#pragma unroll
            for (int i = 0; i < 2; i++) {
                int row = mb + wm * 64 + mt * 16 + (lane >> 2) + i * 8;
                int bb = row >> 10, t = row & 1023;
#pragma unroll
                for (int nt = 0; nt < 4; nt++) {
                    int d = wn * 32 + nt * 8 + (lane & 3) * 2;
                    float a0 = acc[mt][nt][2 * i], a1 = acc[mt][nt][2 * i + 1];
                    if (region == 2) {
                        size_t dst = ((size_t)(bb * NHEADS + hh) * KVLEN + XLLEN + t) * HD + d;
                        *(__half2*)&g_vh[dst] = __floats2half2_rn(a0, a1);
                    } else {
                        int dp = d >> 1;
                        float cv = cosb[t * 64 + dp], sv = sinb[t * 64 + dp];
                        float o0 = a0 * cv - a1 * sv;
                        float o1 = a0 * sv + a1 * cv;
                        if (region == 0) {
                            size_t dst = ((size_t)(bb * NHEADS + hh) * TQ + t) * HD + d;
                            *(__half2*)&g_qh[dst] = __floats2half2_rn(o0, o1);
                        } else {
                            size_t dst = ((size_t)(bb * NHEADS + hh) * KVLEN + XLLEN + t) * HD + d;
                            *(__half2*)&g_kh[dst] = __floats2half2_rn(o0, o1);
                        }
                    }
                }
            }
        }
    }
}

// =====================================================================
// Flash attention FA2: BQ=128, BK=128, D=128, 8 warps, 2-stage KV,
// ONE barrier per tile (post-barrier prefetch into retired buffer).
// softmax exp via ex2.approx.f16x2; P fragments straight from S regs.
// =====================================================================
#define AQSZ   34816                      // 128 rows x 272B
#define AKV    AQSZ
#define AKVSTG 69632                      // K(128x272) + V(128x272)
#define AVOF   34816
#define ATTN_SMEM (AQSZ + 2 * AKVSTG)     // 174080

__global__ __launch_bounds__(256) void attn_kernel(const int* __restrict__ flag)
{
    extern __shared__ __align__(16) char smraw[];
    const uint32_t sb = smem_u32(smraw);
    const int tid = threadIdx.x, w = tid >> 5, lane = tid & 31;
    const int qt = blockIdx.x, bh = blockIdx.y;
    const int b = bh >> 4, h = bh & 15;
    const int qbase = qt * 128;
    const int causal = *flag;

    const __half* Qh = g_qh + (size_t)bh * (TQ * HD);
    const __half* Kh = g_kh + (size_t)bh * (KVLEN * HD);
    const __half* Vh = g_vh + (size_t)bh * (KVLEN * HD);

    int ntile = causal ? (qt + 9) : 16;
    if (ntile > 16) ntile = 16;

    // Q tile (group 0)
#pragma unroll
    for (int i = 0; i < 8; i++) {
        int c = tid + i * 256;
        int row = c >> 4, kc = c & 15;
        cpa16(sb + row * 272 + kc * 16, Qh + (size_t)(qbase + row) * HD + kc * 8);
    }
    cpa_commit();
    // KV tile 0 (group 1)
    {
#pragma unroll
        for (int i = 0; i < 8; i++) {
            int c = tid + i * 256;
            int row = c >> 4, kc = c & 15;
            cpa16(sb + AKV + row * 272 + kc * 16, Kh + (size_t)row * HD + kc * 8);
            cpa16(sb + AKV + AVOF + row * 272 + kc * 16, Vh + (size_t)row * HD + kc * 8);
        }
        cpa_commit();
    }
    cpa_wait1();                 // Q arrived (KV0 may still be in flight)
    __syncthreads();

    // Q fragments register-resident
    uint32_t qf[8][4];
    {
        const uint32_t qrow = (uint32_t)(w * 16 + (lane & 15)) * 272;
#pragma unroll
        for (int ks = 0; ks < 8; ks++)
            ldm4(qf[ks], sb + qrow + ks * 32 + (lane >> 4) * 16);
    }

    float oacc[16][4];
#pragma unroll
    for (int nq = 0; nq < 16; nq++)
#pragma unroll
        for (int e = 0; e < 4; e++) oacc[nq][e] = 0.f;
    float mrow[2] = {-1e30f, -1e30f}, lrow[2] = {0.f, 0.f};

    const float scale2 = 0.12751879523525493f;   // log2(e)/sqrt(128)
    const int roff = KVLEN - TQ;

    for (int kt = 0; kt < ntile; kt++) {
        cpa_wait0();                              // tile kt fully arrived
        __syncthreads();                          // + all warps done reading kt-1
        const uint32_t kvst = sb + AKV + (kt & 1) * AKVSTG;

        if (kt + 1 < ntile) {                     // prefetch kt+1 into retired buf
            const uint32_t st = sb + AKV + ((kt + 1) & 1) * AKVSTG;
            const int kb0 = (kt + 1) * 128;
#pragma unroll
            for (int i = 0; i < 8; i++) {
                int c = tid + i * 256;
                int row = c >> 4, kc = c & 15;
                cpa16(st + row * 272 + kc * 16, Kh + (size_t)(kb0 + row) * HD + kc * 8);
                cpa16(st + AVOF + row * 272 + kc * 16, Vh + (size_t)(kb0 + row) * HD + kc * 8);
            }
            cpa_commit();
        }

        // ---- S = Q K^T ----
        float sacc[16][4];
#pragma unroll
        for (int nt = 0; nt < 16; nt++)
#pragma unroll
            for (int e = 0; e < 4; e++) sacc[nt][e] = 0.f;

        const uint32_t krow = (uint32_t)(lane & 15) * 272;
#pragma unroll
        for (int ks = 0; ks < 8; ks++) {
            const uint32_t koff = ks * 32 + (lane >> 4) * 16;
#pragma unroll
            for (int np = 0; np < 8; np++) {
                uint32_t kf[4];
                ldm4(kf, kvst + krow + np * 16 * 272 + koff);
                mma16816(sacc[2 * np],     qf[ks], kf[0], kf[2]);
                mma16816(sacc[2 * np + 1], qf[ks], kf[1], kf[3]);
            }
        }

        // ---- scale (log2 domain); causal mask under uniform branch ----
#pragma unroll
        for (int nt = 0; nt < 16; nt++)
#pragma unroll
            for (int e = 0; e < 4; e++) sacc[nt][e] *= scale2;
        if (causal) {
            const int kbase = kt * 128;
            const int rglo = qbase + w * 16 + (lane >> 2) + roff;
#pragma unroll
            for (int nt = 0; nt < 16; nt++)
#pragma unroll
                for (int e = 0; e < 4; e++) {
                    int cl = kbase + nt * 8 + (lane & 3) * 2 + (e & 1);
                    if (cl > rglo + (e >> 1) * 8) sacc[nt][e] = -1e30f;
                }
        }

        // ---- register softmax (quad shfl) ----
        float ml[2] = {-1e30f, -1e30f};
#pragma unroll
        for (int nt = 0; nt < 16; nt++) {
            ml[0] = fmaxf(ml[0], fmaxf(sacc[nt][0], sacc[nt][1]));
            ml[1] = fmaxf(ml[1], fmaxf(sacc[nt][2], sacc[nt][3]));
        }
#pragma unroll
        for (int i = 0; i < 2; i++) {
            ml[i] = fmaxf(ml[i], __shfl_xor_sync(0xffffffffu, ml[i], 1));
            ml[i] = fmaxf(ml[i], __shfl_xor_sync(0xffffffffu, ml[i], 2));
        }
        float mn[2], al[2];
#pragma unroll
        for (int i = 0; i < 2; i++) {
            mn[i] = fmaxf(mrow[i], ml[i]);
            al[i] = exp2f(mrow[i] - mn[i]);
            mrow[i] = mn[i];
        }

        // ---- P = exp2(S - m) packed fp16; directly PV A-fragments ----
        float ls[2] = {0.f, 0.f};
        uint32_t pf[8][4];
#pragma unroll
        for (int nt = 0; nt < 16; nt++) {
            uint32_t p01 = ex2h2(sacc[nt][0] - mn[0], sacc[nt][1] - mn[0]);
            uint32_t p23 = ex2h2(sacc[nt][2] - mn[1], sacc[nt][3] - mn[1]);
            pf[nt >> 1][(nt & 1) * 2 + 0] = p01;
            pf[nt >> 1][(nt & 1) * 2 + 1] = p23;
            float2 f0 = __half22float2(*(__half2*)&p01);
            float2 f1 = __half22float2(*(__half2*)&p23);
            ls[0] += f0.x + f0.y;
            ls[1] += f1.x + f1.y;
        }
#pragma unroll
        for (int i = 0; i < 2; i++) {
            ls[i] += __shfl_xor_sync(0xffffffffu, ls[i], 1);
            ls[i] += __shfl_xor_sync(0xffffffffu, ls[i], 2);
            lrow[i] = lrow[i] * al[i] + ls[i];
        }
#pragma unroll
        for (int nq = 0; nq < 16; nq++) {
            oacc[nq][0] *= al[0]; oacc[nq][1] *= al[0];
            oacc[nq][2] *= al[1]; oacc[nq][3] *= al[1];
        }

        // ---- O += P V ----
#pragma unroll
        for (int kp = 0; kp < 8; kp++) {
            const uint32_t vrow = (uint32_t)(kp * 16 + (lane & 15)) * 272 + (lane >> 4) * 16;
#pragma unroll
            for (int np = 0; np < 8; np++) {
                uint32_t vb[4];
                ldm4t(vb, kvst + AVOF + vrow + np * 32);
                mma16816(oacc[2 * np],     pf[kp], vb[0], vb[1]);
                mma16816(oacc[2 * np + 1], pf[kp], vb[2], vb[3]);
            }
        }
    }

    // ---- epilogue: O / l -> fp16 y ----
#pragma unroll
    for (int i = 0; i < 2; i++) {
        float inv = 1.0f / lrow[i];
        int rl = w * 16 + (lane >> 2) + i * 8;
        __half* Yp = g_yh + (size_t)(b * TQ + qbase + rl) * D_MODEL + h * HD;
#pragma unroll
        for (int nq = 0; nq < 16; nq++) {
            int col = nq * 8 + (lane & 3) * 2;
            *(__half2*)(Yp + col) =
                __floats2half2_rn(oacc[nq][2 * i] * inv, oacc[nq][2 * i + 1] * inv);
        }
    }
}

// =====================================================================
// launch
// =====================================================================
extern "C" void kernel_launch(void* const* d_in, const int* in_sizes, int n_in,
                              void* d_out, int out_size)
{
    const float* x     = (const float*)d_in[0];
    const float* cosb  = (const float*)d_in[1];
    const float* sinb  = (const float*)d_in[2];
    const float* kxl   = (const float*)d_in[3];
    const float* vxl   = (const float*)d_in[4];
    const float* pos   = (const float*)d_in[5];
    const float* wqkv  = (const float*)d_in[6];
    const float* wproj = (const float*)d_in[7];
    const int*   flag  = (const int*)d_in[8];
    float*       out   = (float*)d_out;

    __half *ah, *bh, *bp, *yh;
    cudaGetSymbolAddress((void**)&ah, g_ah);
    cudaGetSymbolAddress((void**)&bh, g_bh);
    cudaGetSymbolAddress((void**)&bp, g_bp);
    cudaGetSymbolAddress((void**)&yh, g_yh);

    cudaFuncSetAttribute(attn_kernel, cudaFuncAttributeMaxDynamicSharedMemorySize, ATTN_SMEM);
    cudaFuncSetAttribute(gemm_mma<0>, cudaFuncAttributeMaxDynamicSharedMemorySize, GEMM_SMEM);
    cudaFuncSetAttribute(gemm_mma<1>, cudaFuncAttributeMaxDynamicSharedMemorySize, GEMM_SMEM);

    // 1) convert x + wqkv only (qkv GEMM inputs)
    prep1_kernel<<<8192, 256>>>(x, wqkv);

    // 2) qkv GEMM (fused RoPE + scatter) + overlapped aux CTAs
    //    (wproj conversion + XL K/V prep) in blockIdx.y == 16
    gemm_mma<1><<<dim3(3 * D_MODEL / 128, MROWS / 128 + 1), 256, GEMM_SMEM>>>(
        ah, bh, nullptr, cosb, sinb, wproj, kxl, vxl, pos,
        MROWS, 3 * D_MODEL, D_MODEL);

    // 3) flash attention -> fp16 y
    attn_kernel<<<dim3(TQ / 128, BATCH * NHEADS), 256, ATTN_SMEM>>>(flag);

    // 4) out = y @ w_proj^T
    gemm_mma<0><<<dim3(D_MODEL / 128, MROWS / 128), 256, GEMM_SMEM>>>(
        yh, bp, out, nullptr, nullptr, nullptr, nullptr, nullptr, nullptr,
        MROWS, D_MODEL, D_MODEL);
}